// round 1
// baseline (speedup 1.0000x reference)
#include <cuda_runtime.h>
#include <math.h>
#include <stdint.h>

// ---------------- problem dims ----------------
#define NB   16
#define NS   768
#define ND   384
#define NH   12
#define NDK  32
#define NFF  1024
#define NL   6
#define NML  768
#define NNC  10
#define NBS  (NB*NS)          // 12288 rows

// ---------------- scratch (single static device buffer) ----------------
// X, H, Q, K, V, A : NBS*ND each ; FF : NBS*NFF ; PT : 4*NBS*96 ; PS : 4*NBS
// PD : NB*4*ND ; C1 : NB*ND ; C2 : NB*192
#define OFF_X   ((size_t)0)
#define OFF_H   (OFF_X  + (size_t)NBS*ND)
#define OFF_Q   (OFF_H  + (size_t)NBS*ND)
#define OFF_K   (OFF_Q  + (size_t)NBS*ND)
#define OFF_V   (OFF_K  + (size_t)NBS*ND)
#define OFF_A   (OFF_V  + (size_t)NBS*ND)
#define OFF_FF  (OFF_A  + (size_t)NBS*ND)
#define OFF_PT  (OFF_FF + (size_t)NBS*NFF)
#define OFF_PS  (OFF_PT + (size_t)4*NBS*96)
#define OFF_PD  (OFF_PS + (size_t)4*NBS)
#define OFF_C1  (OFF_PD + (size_t)NB*4*ND)
#define OFF_C2  (OFF_C1 + (size_t)NB*ND)
#define SCRATCH_TOTAL (OFF_C2 + (size_t)NB*192)

static __device__ float g_scratch[SCRATCH_TOTAL];

// ---------------- embed: x = token_emb[ids] + pos_enc ----------------
__global__ void embed_kernel(const float* __restrict__ te, const float* __restrict__ pe,
                             const int* __restrict__ ids, float* __restrict__ x) {
    int row = blockIdx.x;            // 0..NBS-1
    int d   = threadIdx.x;           // 0..ND-1
    int s   = row % NS;
    int id  = ids[row];
    x[(size_t)row * ND + d] = te[(size_t)id * ND + d] + pe[(size_t)s * ND + d];
}

// ---------------- layernorm: one block (128 thr) per row ----------------
__device__ __forceinline__ float block_sum128(float v, float* red) {
    #pragma unroll
    for (int o = 16; o > 0; o >>= 1) v += __shfl_xor_sync(0xffffffffu, v, o);
    int w = threadIdx.x >> 5;
    if ((threadIdx.x & 31) == 0) red[w] = v;
    __syncthreads();
    float t = red[0] + red[1] + red[2] + red[3];
    __syncthreads();
    return t;
}

__global__ void ln_kernel(const float* __restrict__ in, float* __restrict__ out,
                          const float* __restrict__ g, const float* __restrict__ b) {
    __shared__ float red[4];
    int row = blockIdx.x;
    const float* p = in + (size_t)row * ND;
    float s = 0.f;
    for (int d = threadIdx.x; d < ND; d += 128) s += p[d];
    float mean = block_sum128(s, red) * (1.f / ND);
    float vs = 0.f;
    for (int d = threadIdx.x; d < ND; d += 128) { float t = p[d] - mean; vs += t * t; }
    float var = block_sum128(vs, red) * (1.f / ND);
    float inv = rsqrtf(var + 1e-5f);
    float* o = out + (size_t)row * ND;
    for (int d = threadIdx.x; d < ND; d += 128)
        o[d] = (p[d] - mean) * inv * g[d] + b[d];
}

// ---------------- generic SGEMM: C = epi(A[M,K] @ W[K,N] + bias) ----------------
// EPI: 0 = none, 1 = exact gelu, 2 = residual add (res + acc), 3 = tanh
template<int EPI>
__global__ void gemm_kernel(const float* __restrict__ A, const float* __restrict__ W,
                            const float* __restrict__ bias, const float* __restrict__ res,
                            float* __restrict__ C, int M, int N, int K) {
    __shared__ float As[16][65];   // [kk][row], padded
    __shared__ float Bs[16][64];   // [kk][col]
    const int brow = blockIdx.y * 64;
    const int bcol = blockIdx.x * 64;
    const int t  = threadIdx.x;        // 256
    const int ty = t >> 4, tx = t & 15;
    float acc[4][4] = {};
    for (int k0 = 0; k0 < K; k0 += 16) {
        #pragma unroll
        for (int l = t; l < 1024; l += 256) {
            int r = l >> 4, kk = l & 15;
            int gr = brow + r;
            As[kk][r] = (gr < M) ? A[(size_t)gr * K + k0 + kk] : 0.f;
        }
        #pragma unroll
        for (int l = t; l < 1024; l += 256) {
            int kk = l >> 6, c = l & 63;
            int gc = bcol + c;
            Bs[kk][c] = (gc < N) ? W[(size_t)(k0 + kk) * N + gc] : 0.f;
        }
        __syncthreads();
        #pragma unroll
        for (int kk = 0; kk < 16; kk++) {
            float a[4], bvals[4];
            #pragma unroll
            for (int i = 0; i < 4; i++) a[i] = As[kk][ty * 4 + i];
            #pragma unroll
            for (int j = 0; j < 4; j++) bvals[j] = Bs[kk][tx * 4 + j];
            #pragma unroll
            for (int i = 0; i < 4; i++)
                #pragma unroll
                for (int j = 0; j < 4; j++)
                    acc[i][j] += a[i] * bvals[j];
        }
        __syncthreads();
    }
    #pragma unroll
    for (int i = 0; i < 4; i++) {
        int row = brow + ty * 4 + i;
        if (row >= M) continue;
        #pragma unroll
        for (int j = 0; j < 4; j++) {
            int col = bcol + tx * 4 + j;
            if (col >= N) continue;
            float v = acc[i][j] + bias[col];
            if (EPI == 1) v = 0.5f * v * (1.f + erff(v * 0.70710678118654752f));
            else if (EPI == 2) v = res[(size_t)row * N + col] + v;
            else if (EPI == 3) v = tanhf(v);
            C[(size_t)row * N + col] = v;
        }
    }
}

// ---------------- fused attention ----------------
// grid: (NS/QT, NH, NB), block: QT threads, one query row per thread.
// scores = scale * ( q . (k + rel[k - q + ML-1]) ), mask keys where id==0,
// online softmax, out = attn @ V.
#define QT 128
#define KT 64

__global__ void attn_kernel(const float* __restrict__ q, const float* __restrict__ k,
                            const float* __restrict__ v, const float* __restrict__ rel,
                            const int* __restrict__ ids, float* __restrict__ out) {
    const int q0 = blockIdx.x * QT;
    const int h  = blockIdx.y;
    const int b  = blockIdx.z;
    const int ql = threadIdx.x;
    const int qg = q0 + ql;

    __shared__ float Ks[KT][NDK];
    __shared__ float Vs[KT][NDK];
    __shared__ float Rs[QT + KT - 1][NDK + 1];   // padded: kills stride-128B conflict
    __shared__ int   Ms[KT];

    float qv[NDK];
    const float* qp = q + ((size_t)(b * NS + qg)) * ND + h * NDK;
    #pragma unroll
    for (int d = 0; d < NDK; d++) qv[d] = qp[d];

    float m = -INFINITY, l = 0.f;
    float acc[NDK];
    #pragma unroll
    for (int d = 0; d < NDK; d++) acc[d] = 0.f;
    const float scale = 0.17677669529663689f;    // 1/sqrt(32)

    for (int k0 = 0; k0 < NS; k0 += KT) {
        for (int idx = threadIdx.x; idx < KT * NDK; idx += QT) {
            int kk = idx >> 5, d = idx & 31;
            size_t off = ((size_t)(b * NS + k0 + kk)) * ND + h * NDK + d;
            Ks[kk][d] = k[off];
            Vs[kk][d] = v[off];
        }
        for (int idx = threadIdx.x; idx < (QT + KT - 1) * NDK; idx += QT) {
            int r = idx >> 5, d = idx & 31;
            int g = k0 - q0 + (NML - 1) - (QT - 1) + r;   // always in [0, 2*ML-2]
            Rs[r][d] = rel[(size_t)g * NDK + d];
        }
        if (threadIdx.x < KT) Ms[threadIdx.x] = ids[b * NS + k0 + threadIdx.x];
        __syncthreads();

        for (int kk = 0; kk < KT; kk++) {
            const int rr = kk - ql + (QT - 1);
            float s = 0.f;
            #pragma unroll
            for (int d = 0; d < NDK; d++)
                s += qv[d] * (Ks[kk][d] + Rs[rr][d]);
            s *= scale;
            if (Ms[kk] != 0) {
                if (s <= m) {
                    float p = __expf(s - m);
                    l += p;
                    #pragma unroll
                    for (int d = 0; d < NDK; d++) acc[d] += p * Vs[kk][d];
                } else {
                    float c = __expf(m - s);   // exp(-inf)=0 on first hit
                    m = s;
                    l = l * c + 1.f;
                    #pragma unroll
                    for (int d = 0; d < NDK; d++) acc[d] = acc[d] * c + Vs[kk][d];
                }
            }
        }
        __syncthreads();
    }
    float inv = 1.f / l;
    float* op = out + ((size_t)(b * NS + qg)) * ND + h * NDK;
    #pragma unroll
    for (int d = 0; d < NDK; d++) op[d] = acc[d] * inv;
}

// ---------------- pooling score: s = tanh(x@pw1)@pw2 + pb2 (warp per row) ----------------
__global__ void pool_score_kernel(const float* __restrict__ tmp, const float* __restrict__ pw2,
                                  const float* __restrict__ pb2, float* __restrict__ scores) {
    int gid = blockIdx.x * (blockDim.x >> 5) + (threadIdx.x >> 5);
    if (gid >= 4 * NBS) return;
    int head = gid / NBS;
    int lane = threadIdx.x & 31;
    const float* p = tmp + (size_t)gid * 96;
    float s = 0.f;
    for (int j = lane; j < 96; j += 32) s += p[j] * pw2[head * 96 + j];
    #pragma unroll
    for (int o = 16; o > 0; o >>= 1) s += __shfl_xor_sync(0xffffffffu, s, o);
    if (lane == 0) scores[gid] = s + pb2[head];
}

// ---------------- pooling: masked softmax over seq + weighted sum ----------------
__global__ void pool_kernel(const float* __restrict__ x, const float* __restrict__ scores,
                            const int* __restrict__ ids, float* __restrict__ pooled) {
    const int head = blockIdx.x;
    const int b    = blockIdx.y;
    __shared__ float ps[NS];
    __shared__ float red[8];
    const float* sc = scores + (size_t)head * NBS + (size_t)b * NS;

    float m = -INFINITY;
    for (int s = threadIdx.x; s < NS; s += 256) {
        float val = (ids[b * NS + s] == 0) ? -INFINITY : sc[s];
        ps[s] = val;
        m = fmaxf(m, val);
    }
    #pragma unroll
    for (int o = 16; o > 0; o >>= 1) m = fmaxf(m, __shfl_xor_sync(0xffffffffu, m, o));
    if ((threadIdx.x & 31) == 0) red[threadIdx.x >> 5] = m;
    __syncthreads();
    float M = -INFINITY;
    #pragma unroll
    for (int i = 0; i < 8; i++) M = fmaxf(M, red[i]);
    __syncthreads();

    float sum = 0.f;
    for (int s = threadIdx.x; s < NS; s += 256) {
        float p = __expf(ps[s] - M);    // exp(-inf)=0 for masked
        ps[s] = p;
        sum += p;
    }
    #pragma unroll
    for (int o = 16; o > 0; o >>= 1) sum += __shfl_xor_sync(0xffffffffu, sum, o);
    if ((threadIdx.x & 31) == 0) red[threadIdx.x >> 5] = sum;
    __syncthreads();
    float T = 0.f;
    #pragma unroll
    for (int i = 0; i < 8; i++) T += red[i];
    __syncthreads();
    float inv = 1.f / T;

    for (int d = threadIdx.x; d < ND; d += 256) {
        float acc = 0.f;
        const float* xp = x + (size_t)b * NS * ND + d;
        for (int s = 0; s < NS; s++) acc += ps[s] * xp[(size_t)s * ND];
        pooled[(size_t)b * (4 * ND) + head * ND + d] = acc * inv;
    }
}

// ---------------- host-side gemm dispatcher ----------------
static void run_gemm(const float* A, const float* W, const float* bias, const float* res,
                     float* C, int M, int N, int K, int epi) {
    dim3 grid((N + 63) / 64, (M + 63) / 64);
    switch (epi) {
        case 0: gemm_kernel<0><<<grid, 256>>>(A, W, bias, res, C, M, N, K); break;
        case 1: gemm_kernel<1><<<grid, 256>>>(A, W, bias, res, C, M, N, K); break;
        case 2: gemm_kernel<2><<<grid, 256>>>(A, W, bias, res, C, M, N, K); break;
        case 3: gemm_kernel<3><<<grid, 256>>>(A, W, bias, res, C, M, N, K); break;
    }
}

// ---------------- entry ----------------
extern "C" void kernel_launch(void* const* d_in, const int* in_sizes, int n_in,
                              void* d_out, int out_size) {
    const float* te   = (const float*)d_in[0];   // token_emb [V,D]
    const float* pe   = (const float*)d_in[1];   // pos_enc [1,ML,D]
    const float* wq   = (const float*)d_in[2];
    const float* bq   = (const float*)d_in[3];
    const float* wk   = (const float*)d_in[4];
    const float* bk   = (const float*)d_in[5];
    const float* wv   = (const float*)d_in[6];
    const float* bv   = (const float*)d_in[7];
    const float* wo   = (const float*)d_in[8];
    const float* bo   = (const float*)d_in[9];
    const float* rel  = (const float*)d_in[10];  // [L, 2ML-1, DK]
    const float* g1   = (const float*)d_in[11];
    const float* b1   = (const float*)d_in[12];
    const float* g2   = (const float*)d_in[13];
    const float* b2   = (const float*)d_in[14];
    const float* fw1  = (const float*)d_in[15];
    const float* fb1  = (const float*)d_in[16];
    const float* fw2  = (const float*)d_in[17];
    const float* fb2  = (const float*)d_in[18];
    const float* fg   = (const float*)d_in[19];
    const float* fbn  = (const float*)d_in[20];
    const float* pw1  = (const float*)d_in[21];  // [4,D,96]
    const float* pb1  = (const float*)d_in[22];  // [4,96]
    const float* pw2  = (const float*)d_in[23];  // [4,96,1]
    const float* pb2  = (const float*)d_in[24];  // [4,1]
    const float* cw1  = (const float*)d_in[25];  // [1536,384]
    const float* cb1  = (const float*)d_in[26];
    const float* cw2  = (const float*)d_in[27];  // [384,192]
    const float* cb2  = (const float*)d_in[28];
    const float* cw3  = (const float*)d_in[29];  // [192,10]
    const float* cb3  = (const float*)d_in[30];
    const int*   ids  = (const int*)d_in[31];    // [B,S]

    float* S;
    cudaGetSymbolAddress((void**)&S, g_scratch);
    float* X  = S + OFF_X;
    float* HB = S + OFF_H;
    float* Q  = S + OFF_Q;
    float* K  = S + OFF_K;
    float* V  = S + OFF_V;
    float* AB = S + OFF_A;
    float* FB = S + OFF_FF;
    float* PT = S + OFF_PT;
    float* PS = S + OFF_PS;
    float* PD = S + OFF_PD;
    float* C1 = S + OFF_C1;
    float* C2 = S + OFF_C2;

    embed_kernel<<<NBS, ND>>>(te, pe, ids, X);

    for (int l = 0; l < NL; l++) {
        const size_t wOff = (size_t)l * ND * ND;
        const size_t dOff = (size_t)l * ND;
        ln_kernel<<<NBS, 128>>>(X, HB, g1 + dOff, b1 + dOff);
        run_gemm(HB, wq + wOff, bq + dOff, nullptr, Q, NBS, ND, ND, 0);
        run_gemm(HB, wk + wOff, bk + dOff, nullptr, K, NBS, ND, ND, 0);
        run_gemm(HB, wv + wOff, bv + dOff, nullptr, V, NBS, ND, ND, 0);
        attn_kernel<<<dim3(NS / QT, NH, NB), QT>>>(
            Q, K, V, rel + (size_t)l * (2 * NML - 1) * NDK, ids, AB);
        run_gemm(AB, wo + wOff, bo + dOff, X, X, NBS, ND, ND, 2);
        ln_kernel<<<NBS, 128>>>(X, HB, g2 + dOff, b2 + dOff);
        run_gemm(HB, fw1 + (size_t)l * ND * NFF, fb1 + (size_t)l * NFF, nullptr, FB,
                 NBS, NFF, ND, 1);
        run_gemm(FB, fw2 + (size_t)l * NFF * ND, fb2 + dOff, X, X, NBS, ND, NFF, 2);
    }

    // final LN -> HB (this is the "x" used by pooling)
    ln_kernel<<<NBS, 128>>>(X, HB, fg, fbn);

    for (int i = 0; i < 4; i++)
        run_gemm(HB, pw1 + (size_t)i * ND * 96, pb1 + (size_t)i * 96, nullptr,
                 PT + (size_t)i * NBS * 96, NBS, 96, ND, 3);
    pool_score_kernel<<<(4 * NBS + 3) / 4, 128>>>(PT, pw2, pb2, PS);
    pool_kernel<<<dim3(4, NB), 256>>>(HB, PS, ids, PD);

    run_gemm(PD, cw1, cb1, nullptr, C1, NB, ND, 4 * ND, 1);
    run_gemm(C1, cw2, cb2, nullptr, C2, NB, 192, ND, 1);
    run_gemm(C2, cw3, cb3, nullptr, (float*)d_out, NB, NNC, 192, 0);
}

// round 2
// speedup vs baseline: 1.5747x; 1.5747x over previous
#include <cuda_runtime.h>
#include <math.h>
#include <stdint.h>

// ---------------- problem dims ----------------
#define NB   16
#define NS   768
#define ND   384
#define NH   12
#define NDK  32
#define NFF  1024
#define NL   6
#define NML  768
#define NNC  10
#define NBS  (NB*NS)          // 12288 rows

// ---------------- scratch ----------------
#define OFF_X   ((size_t)0)
#define OFF_H   (OFF_X  + (size_t)NBS*ND)
#define OFF_Q   (OFF_H  + (size_t)NBS*ND)
#define OFF_K   (OFF_Q  + (size_t)NBS*ND)
#define OFF_V   (OFF_K  + (size_t)NBS*ND)
#define OFF_A   (OFF_V  + (size_t)NBS*ND)
#define OFF_FF  (OFF_A  + (size_t)NBS*ND)
#define OFF_PT  (OFF_FF + (size_t)NBS*NFF)
#define OFF_PS  (OFF_PT + (size_t)4*NBS*96)
#define OFF_PD  (OFF_PS + (size_t)4*NBS)
#define OFF_C1  (OFF_PD + (size_t)NB*4*ND)
#define OFF_C2  (OFF_C1 + (size_t)NB*ND)
#define SCRATCH_TOTAL (OFF_C2 + (size_t)NB*192)

static __device__ float g_scratch[SCRATCH_TOTAL];

// ---------------- embed ----------------
__global__ void embed_kernel(const float* __restrict__ te, const float* __restrict__ pe,
                             const int* __restrict__ ids, float* __restrict__ x) {
    int row = blockIdx.x;
    int d   = threadIdx.x;
    int s   = row % NS;
    int id  = ids[row];
    x[(size_t)row * ND + d] = te[(size_t)id * ND + d] + pe[(size_t)s * ND + d];
}

// ---------------- layernorm ----------------
__device__ __forceinline__ float block_sum128(float v, float* red) {
    #pragma unroll
    for (int o = 16; o > 0; o >>= 1) v += __shfl_xor_sync(0xffffffffu, v, o);
    int w = threadIdx.x >> 5;
    if ((threadIdx.x & 31) == 0) red[w] = v;
    __syncthreads();
    float t = red[0] + red[1] + red[2] + red[3];
    __syncthreads();
    return t;
}

__global__ void ln_kernel(const float* __restrict__ in, float* __restrict__ out,
                          const float* __restrict__ g, const float* __restrict__ b) {
    __shared__ float red[4];
    int row = blockIdx.x;
    const float* p = in + (size_t)row * ND;
    float s = 0.f;
    for (int d = threadIdx.x; d < ND; d += 128) s += p[d];
    float mean = block_sum128(s, red) * (1.f / ND);
    float vs = 0.f;
    for (int d = threadIdx.x; d < ND; d += 128) { float t = p[d] - mean; vs += t * t; }
    float var = block_sum128(vs, red) * (1.f / ND);
    float inv = rsqrtf(var + 1e-5f);
    float* o = out + (size_t)row * ND;
    for (int d = threadIdx.x; d < ND; d += 128)
        o[d] = (p[d] - mean) * inv * g[d] + b[d];
}

// ================= big SGEMM: 128x128 tile, 8x8 micro, double-buffered =================
// Requires M%128==0, N%128==0, K%8==0. EPI: 0 none, 1 gelu, 2 residual
#define BM 128
#define BN 128
#define BKK 8
#define ASTRIDE 132

template<int EPI>
__global__ void __launch_bounds__(256, 2)
gemm128_kernel(const float* __restrict__ A, const float* __restrict__ W,
               const float* __restrict__ bias, const float* __restrict__ res,
               float* __restrict__ C, int M, int N, int K) {
    __shared__ __align__(16) float As[2][BKK][ASTRIDE];
    __shared__ __align__(16) float Bs[2][BKK][BN];

    const int brow = blockIdx.y * BM;
    const int bcol = blockIdx.x * BN;
    const int t  = threadIdx.x;
    const int ty = t >> 4;        // 0..15 -> row group (8 rows)
    const int tx = t & 15;        // 0..15 -> col group (8 cols)

    // A-load mapping: row = t>>1 (0..127), kq = t&1 (which float4 in the 8-wide k slab)
    const int ar = t >> 1;
    const int akq = (t & 1) * 4;
    // B-load mapping: k = t>>5 (0..7), c = (t&31)*4
    const int bk = t >> 5;
    const int bc = (t & 31) * 4;

    const int nt = K / BKK;

    float acc[8][8];
    #pragma unroll
    for (int i = 0; i < 8; i++)
        #pragma unroll
        for (int j = 0; j < 8; j++) acc[i][j] = 0.f;

    // ---- prologue: tile 0 -> buf 0 ----
    {
        float4 av = *(const float4*)&A[(size_t)(brow + ar) * K + akq];
        As[0][akq + 0][ar] = av.x;
        As[0][akq + 1][ar] = av.y;
        As[0][akq + 2][ar] = av.z;
        As[0][akq + 3][ar] = av.w;
        float4 bv = *(const float4*)&W[(size_t)bk * N + bcol + bc];
        *(float4*)&Bs[0][bk][bc] = bv;
    }
    __syncthreads();

    for (int tt = 0; tt < nt; tt++) {
        const int cur = tt & 1;
        const int nxt = cur ^ 1;
        float4 av, bv;
        const bool more = (tt + 1 < nt);
        if (more) {
            const int k0 = (tt + 1) * BKK;
            av = *(const float4*)&A[(size_t)(brow + ar) * K + k0 + akq];
            bv = *(const float4*)&W[(size_t)(k0 + bk) * N + bcol + bc];
        }
        #pragma unroll
        for (int kk = 0; kk < BKK; kk++) {
            float4 a0 = *(const float4*)&As[cur][kk][ty * 8];
            float4 a1 = *(const float4*)&As[cur][kk][ty * 8 + 4];
            float4 b0 = *(const float4*)&Bs[cur][kk][tx * 8];
            float4 b1 = *(const float4*)&Bs[cur][kk][tx * 8 + 4];
            float a[8] = {a0.x, a0.y, a0.z, a0.w, a1.x, a1.y, a1.z, a1.w};
            float b[8] = {b0.x, b0.y, b0.z, b0.w, b1.x, b1.y, b1.z, b1.w};
            #pragma unroll
            for (int i = 0; i < 8; i++)
                #pragma unroll
                for (int j = 0; j < 8; j++)
                    acc[i][j] += a[i] * b[j];
        }
        if (more) {
            As[nxt][akq + 0][ar] = av.x;
            As[nxt][akq + 1][ar] = av.y;
            As[nxt][akq + 2][ar] = av.z;
            As[nxt][akq + 3][ar] = av.w;
            *(float4*)&Bs[nxt][bk][bc] = bv;
        }
        __syncthreads();
    }

    // ---- epilogue ----
    #pragma unroll
    for (int i = 0; i < 8; i++) {
        const int row = brow + ty * 8 + i;
        #pragma unroll
        for (int jj = 0; jj < 2; jj++) {
            const int col = bcol + tx * 8 + jj * 4;
            float4 v;
            float* vp = &v.x;
            #pragma unroll
            for (int j = 0; j < 4; j++) {
                float val = acc[i][jj * 4 + j] + bias[col + j];
                if (EPI == 1) val = 0.5f * val * (1.f + erff(val * 0.70710678118654752f));
                vp[j] = val;
            }
            if (EPI == 2) {
                float4 r = *(const float4*)&res[(size_t)row * N + col];
                v.x += r.x; v.y += r.y; v.z += r.z; v.w += r.w;
            }
            *(float4*)&C[(size_t)row * N + col] = v;
        }
    }
}

// ---------------- small guarded SGEMM (pool/classifier) ----------------
// EPI: 0 none, 1 gelu, 3 tanh
template<int EPI>
__global__ void gemm_kernel(const float* __restrict__ A, const float* __restrict__ W,
                            const float* __restrict__ bias,
                            float* __restrict__ C, int M, int N, int K) {
    __shared__ float As[16][65];
    __shared__ float Bs[16][64];
    const int brow = blockIdx.y * 64;
    const int bcol = blockIdx.x * 64;
    const int t  = threadIdx.x;
    const int ty = t >> 4, tx = t & 15;
    float acc[4][4] = {};
    for (int k0 = 0; k0 < K; k0 += 16) {
        #pragma unroll
        for (int l = t; l < 1024; l += 256) {
            int r = l >> 4, kk = l & 15;
            int gr = brow + r;
            As[kk][r] = (gr < M && k0 + kk < K) ? A[(size_t)gr * K + k0 + kk] : 0.f;
        }
        #pragma unroll
        for (int l = t; l < 1024; l += 256) {
            int kk = l >> 6, c = l & 63;
            int gc = bcol + c;
            Bs[kk][c] = (gc < N && k0 + kk < K) ? W[(size_t)(k0 + kk) * N + gc] : 0.f;
        }
        __syncthreads();
        #pragma unroll
        for (int kk = 0; kk < 16; kk++) {
            float a[4], bvals[4];
            #pragma unroll
            for (int i = 0; i < 4; i++) a[i] = As[kk][ty * 4 + i];
            #pragma unroll
            for (int j = 0; j < 4; j++) bvals[j] = Bs[kk][tx * 4 + j];
            #pragma unroll
            for (int i = 0; i < 4; i++)
                #pragma unroll
                for (int j = 0; j < 4; j++)
                    acc[i][j] += a[i] * bvals[j];
        }
        __syncthreads();
    }
    #pragma unroll
    for (int i = 0; i < 4; i++) {
        int row = brow + ty * 4 + i;
        if (row >= M) continue;
        #pragma unroll
        for (int j = 0; j < 4; j++) {
            int col = bcol + tx * 4 + j;
            if (col >= N) continue;
            float v = acc[i][j] + bias[col];
            if (EPI == 1) v = 0.5f * v * (1.f + erff(v * 0.70710678118654752f));
            else if (EPI == 3) v = tanhf(v);
            C[(size_t)row * N + col] = v;
        }
    }
}

// ---------------- fused attention ----------------
#define QT 128
#define KT 64

__global__ void attn_kernel(const float* __restrict__ q, const float* __restrict__ k,
                            const float* __restrict__ v, const float* __restrict__ rel,
                            const int* __restrict__ ids, float* __restrict__ out) {
    const int q0 = blockIdx.x * QT;
    const int h  = blockIdx.y;
    const int b  = blockIdx.z;
    const int ql = threadIdx.x;
    const int qg = q0 + ql;

    __shared__ float Ks[KT][NDK];
    __shared__ float Vs[KT][NDK];
    __shared__ float Rs[QT + KT - 1][NDK + 1];
    __shared__ int   Ms[KT];

    float qv[NDK];
    const float* qp = q + ((size_t)(b * NS + qg)) * ND + h * NDK;
    #pragma unroll
    for (int d = 0; d < NDK; d++) qv[d] = qp[d];

    float m = -INFINITY, l = 0.f;
    float acc[NDK];
    #pragma unroll
    for (int d = 0; d < NDK; d++) acc[d] = 0.f;
    const float scale = 0.17677669529663689f;

    for (int k0 = 0; k0 < NS; k0 += KT) {
        for (int idx = threadIdx.x; idx < KT * NDK; idx += QT) {
            int kk = idx >> 5, d = idx & 31;
            size_t off = ((size_t)(b * NS + k0 + kk)) * ND + h * NDK + d;
            Ks[kk][d] = k[off];
            Vs[kk][d] = v[off];
        }
        for (int idx = threadIdx.x; idx < (QT + KT - 1) * NDK; idx += QT) {
            int r = idx >> 5, d = idx & 31;
            int g = k0 - q0 + (NML - 1) - (QT - 1) + r;
            Rs[r][d] = rel[(size_t)g * NDK + d];
        }
        if (threadIdx.x < KT) Ms[threadIdx.x] = ids[b * NS + k0 + threadIdx.x];
        __syncthreads();

        for (int kk = 0; kk < KT; kk++) {
            const int rr = kk - ql + (QT - 1);
            float s = 0.f;
            #pragma unroll
            for (int d = 0; d < NDK; d++)
                s += qv[d] * (Ks[kk][d] + Rs[rr][d]);
            s *= scale;
            if (Ms[kk] != 0) {
                if (s <= m) {
                    float p = __expf(s - m);
                    l += p;
                    #pragma unroll
                    for (int d = 0; d < NDK; d++) acc[d] += p * Vs[kk][d];
                } else {
                    float c = __expf(m - s);
                    m = s;
                    l = l * c + 1.f;
                    #pragma unroll
                    for (int d = 0; d < NDK; d++) acc[d] = acc[d] * c + Vs[kk][d];
                }
            }
        }
        __syncthreads();
    }
    float inv = 1.f / l;
    float* op = out + ((size_t)(b * NS + qg)) * ND + h * NDK;
    #pragma unroll
    for (int d = 0; d < NDK; d++) op[d] = acc[d] * inv;
}

// ---------------- pooling ----------------
__global__ void pool_score_kernel(const float* __restrict__ tmp, const float* __restrict__ pw2,
                                  const float* __restrict__ pb2, float* __restrict__ scores) {
    int gid = blockIdx.x * (blockDim.x >> 5) + (threadIdx.x >> 5);
    if (gid >= 4 * NBS) return;
    int head = gid / NBS;
    int lane = threadIdx.x & 31;
    const float* p = tmp + (size_t)gid * 96;
    float s = 0.f;
    for (int j = lane; j < 96; j += 32) s += p[j] * pw2[head * 96 + j];
    #pragma unroll
    for (int o = 16; o > 0; o >>= 1) s += __shfl_xor_sync(0xffffffffu, s, o);
    if (lane == 0) scores[gid] = s + pb2[head];
}

__global__ void pool_kernel(const float* __restrict__ x, const float* __restrict__ scores,
                            const int* __restrict__ ids, float* __restrict__ pooled) {
    const int head = blockIdx.x;
    const int b    = blockIdx.y;
    __shared__ float ps[NS];
    __shared__ float red[8];
    const float* sc = scores + (size_t)head * NBS + (size_t)b * NS;

    float m = -INFINITY;
    for (int s = threadIdx.x; s < NS; s += 256) {
        float val = (ids[b * NS + s] == 0) ? -INFINITY : sc[s];
        ps[s] = val;
        m = fmaxf(m, val);
    }
    #pragma unroll
    for (int o = 16; o > 0; o >>= 1) m = fmaxf(m, __shfl_xor_sync(0xffffffffu, m, o));
    if ((threadIdx.x & 31) == 0) red[threadIdx.x >> 5] = m;
    __syncthreads();
    float M = -INFINITY;
    #pragma unroll
    for (int i = 0; i < 8; i++) M = fmaxf(M, red[i]);
    __syncthreads();

    float sum = 0.f;
    for (int s = threadIdx.x; s < NS; s += 256) {
        float p = __expf(ps[s] - M);
        ps[s] = p;
        sum += p;
    }
    #pragma unroll
    for (int o = 16; o > 0; o >>= 1) sum += __shfl_xor_sync(0xffffffffu, sum, o);
    if ((threadIdx.x & 31) == 0) red[threadIdx.x >> 5] = sum;
    __syncthreads();
    float T = 0.f;
    #pragma unroll
    for (int i = 0; i < 8; i++) T += red[i];
    __syncthreads();
    float inv = 1.f / T;

    for (int d = threadIdx.x; d < ND; d += 256) {
        float acc = 0.f;
        const float* xp = x + (size_t)b * NS * ND + d;
        for (int s = 0; s < NS; s++) acc += ps[s] * xp[(size_t)s * ND];
        pooled[(size_t)b * (4 * ND) + head * ND + d] = acc * inv;
    }
}

// ---------------- dispatchers ----------------
static void run_big_gemm(const float* A, const float* W, const float* bias, const float* res,
                         float* C, int M, int N, int K, int epi) {
    dim3 grid(N / BN, M / BM);
    switch (epi) {
        case 0: gemm128_kernel<0><<<grid, 256>>>(A, W, bias, res, C, M, N, K); break;
        case 1: gemm128_kernel<1><<<grid, 256>>>(A, W, bias, res, C, M, N, K); break;
        case 2: gemm128_kernel<2><<<grid, 256>>>(A, W, bias, res, C, M, N, K); break;
    }
}

static void run_small_gemm(const float* A, const float* W, const float* bias,
                           float* C, int M, int N, int K, int epi) {
    dim3 grid((N + 63) / 64, (M + 63) / 64);
    switch (epi) {
        case 0: gemm_kernel<0><<<grid, 256>>>(A, W, bias, C, M, N, K); break;
        case 1: gemm_kernel<1><<<grid, 256>>>(A, W, bias, C, M, N, K); break;
        case 3: gemm_kernel<3><<<grid, 256>>>(A, W, bias, C, M, N, K); break;
    }
}

// ---------------- entry ----------------
extern "C" void kernel_launch(void* const* d_in, const int* in_sizes, int n_in,
                              void* d_out, int out_size) {
    const float* te   = (const float*)d_in[0];
    const float* pe   = (const float*)d_in[1];
    const float* wq   = (const float*)d_in[2];
    const float* bq   = (const float*)d_in[3];
    const float* wk   = (const float*)d_in[4];
    const float* bk   = (const float*)d_in[5];
    const float* wv   = (const float*)d_in[6];
    const float* bv   = (const float*)d_in[7];
    const float* wo   = (const float*)d_in[8];
    const float* bo   = (const float*)d_in[9];
    const float* rel  = (const float*)d_in[10];
    const float* g1   = (const float*)d_in[11];
    const float* b1   = (const float*)d_in[12];
    const float* g2   = (const float*)d_in[13];
    const float* b2   = (const float*)d_in[14];
    const float* fw1  = (const float*)d_in[15];
    const float* fb1  = (const float*)d_in[16];
    const float* fw2  = (const float*)d_in[17];
    const float* fb2  = (const float*)d_in[18];
    const float* fg   = (const float*)d_in[19];
    const float* fbn  = (const float*)d_in[20];
    const float* pw1  = (const float*)d_in[21];
    const float* pb1  = (const float*)d_in[22];
    const float* pw2  = (const float*)d_in[23];
    const float* pb2  = (const float*)d_in[24];
    const float* cw1  = (const float*)d_in[25];
    const float* cb1  = (const float*)d_in[26];
    const float* cw2  = (const float*)d_in[27];
    const float* cb2  = (const float*)d_in[28];
    const float* cw3  = (const float*)d_in[29];
    const float* cb3  = (const float*)d_in[30];
    const int*   ids  = (const int*)d_in[31];

    float* S;
    cudaGetSymbolAddress((void**)&S, g_scratch);
    float* X  = S + OFF_X;
    float* HB = S + OFF_H;
    float* Q  = S + OFF_Q;
    float* K  = S + OFF_K;
    float* V  = S + OFF_V;
    float* AB = S + OFF_A;
    float* FB = S + OFF_FF;
    float* PT = S + OFF_PT;
    float* PS = S + OFF_PS;
    float* PD = S + OFF_PD;
    float* C1 = S + OFF_C1;
    float* C2 = S + OFF_C2;

    embed_kernel<<<NBS, ND>>>(te, pe, ids, X);

    for (int l = 0; l < NL; l++) {
        const size_t wOff = (size_t)l * ND * ND;
        const size_t dOff = (size_t)l * ND;
        ln_kernel<<<NBS, 128>>>(X, HB, g1 + dOff, b1 + dOff);
        run_big_gemm(HB, wq + wOff, bq + dOff, nullptr, Q, NBS, ND, ND, 0);
        run_big_gemm(HB, wk + wOff, bk + dOff, nullptr, K, NBS, ND, ND, 0);
        run_big_gemm(HB, wv + wOff, bv + dOff, nullptr, V, NBS, ND, ND, 0);
        attn_kernel<<<dim3(NS / QT, NH, NB), QT>>>(
            Q, K, V, rel + (size_t)l * (2 * NML - 1) * NDK, ids, AB);
        run_big_gemm(AB, wo + wOff, bo + dOff, X, X, NBS, ND, ND, 2);
        ln_kernel<<<NBS, 128>>>(X, HB, g2 + dOff, b2 + dOff);
        run_big_gemm(HB, fw1 + (size_t)l * ND * NFF, fb1 + (size_t)l * NFF, nullptr, FB,
                     NBS, NFF, ND, 1);
        run_big_gemm(FB, fw2 + (size_t)l * NFF * ND, fb2 + dOff, X, X, NBS, ND, NFF, 2);
    }

    ln_kernel<<<NBS, 128>>>(X, HB, fg, fbn);

    for (int i = 0; i < 4; i++)
        run_small_gemm(HB, pw1 + (size_t)i * ND * 96, pb1 + (size_t)i * 96,
                       PT + (size_t)i * NBS * 96, NBS, 96, ND, 3);
    pool_score_kernel<<<(4 * NBS + 3) / 4, 128>>>(PT, pw2, pb2, PS);
    pool_kernel<<<dim3(4, NB), 256>>>(HB, PS, ids, PD);

    run_small_gemm(PD, cw1, cb1, C1, NB, ND, 4 * ND, 1);
    run_small_gemm(C1, cw2, cb2, C2, NB, 192, ND, 1);
    run_small_gemm(C2, cw3, cb3, (float*)d_out, NB, NNC, 192, 0);
}

// round 3
// speedup vs baseline: 1.9377x; 1.2305x over previous
#include <cuda_runtime.h>
#include <math.h>
#include <stdint.h>

// ---------------- problem dims ----------------
#define NB   16
#define NS   768
#define ND   384
#define NH   12
#define NDK  32
#define NFF  1024
#define NL   6
#define NML  768
#define NNC  10
#define NBS  (NB*NS)          // 12288 rows

// ---------------- scratch ----------------
#define OFF_X   ((size_t)0)
#define OFF_H   (OFF_X  + (size_t)NBS*ND)
#define OFF_Q   (OFF_H  + (size_t)NBS*ND)
#define OFF_K   (OFF_Q  + (size_t)NBS*ND)
#define OFF_V   (OFF_K  + (size_t)NBS*ND)
#define OFF_A   (OFF_V  + (size_t)NBS*ND)
#define OFF_FF  (OFF_A  + (size_t)NBS*ND)
#define OFF_PT  (OFF_FF + (size_t)NBS*NFF)
#define OFF_PS  (OFF_PT + (size_t)4*NBS*96)
#define OFF_PD  (OFF_PS + (size_t)4*NBS)
#define OFF_C1  (OFF_PD + (size_t)NB*4*ND)
#define OFF_C2  (OFF_C1 + (size_t)NB*ND)
#define SCRATCH_TOTAL (OFF_C2 + (size_t)NB*192)

static __device__ float g_scratch[SCRATCH_TOTAL];

// ---------------- tf32 helpers ----------------
__device__ __forceinline__ float f2tf(float f) {
    uint32_t u;
    asm("cvt.rna.tf32.f32 %0, %1;" : "=r"(u) : "f"(f));
    return __uint_as_float(u);
}

__device__ __forceinline__ void mma_tf32(float* c, const float* a, const float* b) {
    asm volatile(
        "mma.sync.aligned.m16n8k8.row.col.f32.tf32.tf32.f32 "
        "{%0,%1,%2,%3}, {%4,%5,%6,%7}, {%8,%9}, {%0,%1,%2,%3};"
        : "+f"(c[0]), "+f"(c[1]), "+f"(c[2]), "+f"(c[3])
        : "r"(__float_as_uint(a[0])), "r"(__float_as_uint(a[1])),
          "r"(__float_as_uint(a[2])), "r"(__float_as_uint(a[3])),
          "r"(__float_as_uint(b[0])), "r"(__float_as_uint(b[1])));
}

// ---------------- embed ----------------
__global__ void embed_kernel(const float* __restrict__ te, const float* __restrict__ pe,
                             const int* __restrict__ ids, float* __restrict__ x) {
    int row = blockIdx.x;
    int d   = threadIdx.x;
    int s   = row % NS;
    int id  = ids[row];
    x[(size_t)row * ND + d] = te[(size_t)id * ND + d] + pe[(size_t)s * ND + d];
}

// ---------------- layernorm (float4 vectorized, 128 thr/row) ----------------
__device__ __forceinline__ float block_sum128(float v, float* red) {
    #pragma unroll
    for (int o = 16; o > 0; o >>= 1) v += __shfl_xor_sync(0xffffffffu, v, o);
    int w = threadIdx.x >> 5;
    if ((threadIdx.x & 31) == 0) red[w] = v;
    __syncthreads();
    float t = red[0] + red[1] + red[2] + red[3];
    __syncthreads();
    return t;
}

__global__ void ln_kernel(const float* __restrict__ in, float* __restrict__ out,
                          const float* __restrict__ g, const float* __restrict__ b) {
    __shared__ float red[4];
    int row = blockIdx.x;
    const float4* p = (const float4*)(in + (size_t)row * ND);   // 96 float4
    int i = threadIdx.x;      // 0..127, only 0..95 active for vec work
    float4 v4 = (i < 96) ? p[i] : make_float4(0.f, 0.f, 0.f, 0.f);
    float s = v4.x + v4.y + v4.z + v4.w;
    float mean = block_sum128(s, red) * (1.f / ND);
    float vs = 0.f;
    if (i < 96) {
        float a = v4.x - mean, bb = v4.y - mean, c = v4.z - mean, d = v4.w - mean;
        vs = a * a + bb * bb + c * c + d * d;
    }
    float var = block_sum128(vs, red) * (1.f / ND);
    float inv = rsqrtf(var + 1e-5f);
    if (i < 96) {
        float4 gv = ((const float4*)g)[i];
        float4 bv = ((const float4*)b)[i];
        float4 o;
        o.x = (v4.x - mean) * inv * gv.x + bv.x;
        o.y = (v4.y - mean) * inv * gv.y + bv.y;
        o.z = (v4.z - mean) * inv * gv.z + bv.z;
        o.w = (v4.w - mean) * inv * gv.w + bv.w;
        ((float4*)(out + (size_t)row * ND))[i] = o;
    }
}

// ================= tf32 tensor-core GEMM: 128x128 tile, BK=16 =================
// Requires M%128==0, N%128==0, K%16==0. EPI: 0 none, 1 gelu, 2 residual
#define GSTRIDE 136

template<int EPI>
__global__ void __launch_bounds__(256, 2)
gemm_tc_kernel(const float* __restrict__ A, const float* __restrict__ W,
               const float* __restrict__ bias, const float* __restrict__ res,
               float* __restrict__ C, int M, int N, int K) {
    __shared__ float As[2][16][GSTRIDE];   // [k][m] transposed, tf32 bits
    __shared__ float Bs[2][16][GSTRIDE];   // [k][n], tf32 bits

    const int t    = threadIdx.x;
    const int lane = t & 31;
    const int warp = t >> 5;
    const int wm   = (warp & 1) * 64;      // 2 row-warps
    const int wn   = (warp >> 1) * 32;     // 4 col-warps
    const int gid  = lane >> 2;            // 0..7
    const int tig  = lane & 3;             // 0..3
    const int brow = blockIdx.y * 128;
    const int bcol = blockIdx.x * 128;

    // loader mapping
    const int ar = t & 127;                // A row
    const int ak = (t >> 7) * 4;           // k quad base (0 or 4); also +8
    const int bkr = t >> 5;                // B k row (0..7); also +8
    const int bc  = lane * 4;              // B col quad

    const float* Ap = A + (size_t)(brow + ar) * K;

    float acc[4][4][4];
    #pragma unroll
    for (int i = 0; i < 4; i++)
        #pragma unroll
        for (int j = 0; j < 4; j++)
            #pragma unroll
            for (int r = 0; r < 4; r++) acc[i][j][r] = 0.f;

    const int ntiles = K / 16;

    // ---- prologue: tile 0 -> buf 0 ----
    {
        float4 a0 = *(const float4*)&Ap[ak];
        float4 a1 = *(const float4*)&Ap[ak + 8];
        float4 b0 = *(const float4*)&W[(size_t)bkr * N + bcol + bc];
        float4 b1 = *(const float4*)&W[(size_t)(bkr + 8) * N + bcol + bc];
        As[0][ak + 0][ar] = f2tf(a0.x); As[0][ak + 1][ar] = f2tf(a0.y);
        As[0][ak + 2][ar] = f2tf(a0.z); As[0][ak + 3][ar] = f2tf(a0.w);
        As[0][ak + 8][ar] = f2tf(a1.x); As[0][ak + 9][ar] = f2tf(a1.y);
        As[0][ak +10][ar] = f2tf(a1.z); As[0][ak +11][ar] = f2tf(a1.w);
        float4 c0, c1;
        c0.x = f2tf(b0.x); c0.y = f2tf(b0.y); c0.z = f2tf(b0.z); c0.w = f2tf(b0.w);
        c1.x = f2tf(b1.x); c1.y = f2tf(b1.y); c1.z = f2tf(b1.z); c1.w = f2tf(b1.w);
        *(float4*)&Bs[0][bkr][bc]     = c0;
        *(float4*)&Bs[0][bkr + 8][bc] = c1;
    }
    __syncthreads();

    for (int tt = 0; tt < ntiles; tt++) {
        const int cur = tt & 1;
        const int nxt = cur ^ 1;
        const bool more = (tt + 1 < ntiles);
        float4 a0, a1, b0, b1;
        if (more) {
            const int k0 = (tt + 1) * 16;
            a0 = *(const float4*)&Ap[k0 + ak];
            a1 = *(const float4*)&Ap[k0 + ak + 8];
            b0 = *(const float4*)&W[(size_t)(k0 + bkr) * N + bcol + bc];
            b1 = *(const float4*)&W[(size_t)(k0 + bkr + 8) * N + bcol + bc];
        }
        #pragma unroll
        for (int ks = 0; ks < 2; ks++) {
            const int kb = ks * 8;
            float a[4][4], b[4][2];
            #pragma unroll
            for (int mt = 0; mt < 4; mt++) {
                const int m0 = wm + mt * 16 + gid;
                a[mt][0] = As[cur][kb + tig][m0];
                a[mt][1] = As[cur][kb + tig][m0 + 8];
                a[mt][2] = As[cur][kb + tig + 4][m0];
                a[mt][3] = As[cur][kb + tig + 4][m0 + 8];
            }
            #pragma unroll
            for (int nt = 0; nt < 4; nt++) {
                const int n0 = wn + nt * 8 + gid;
                b[nt][0] = Bs[cur][kb + tig][n0];
                b[nt][1] = Bs[cur][kb + tig + 4][n0];
            }
            #pragma unroll
            for (int mt = 0; mt < 4; mt++)
                #pragma unroll
                for (int nt = 0; nt < 4; nt++)
                    mma_tf32(acc[mt][nt], a[mt], b[nt]);
        }
        if (more) {
            As[nxt][ak + 0][ar] = f2tf(a0.x); As[nxt][ak + 1][ar] = f2tf(a0.y);
            As[nxt][ak + 2][ar] = f2tf(a0.z); As[nxt][ak + 3][ar] = f2tf(a0.w);
            As[nxt][ak + 8][ar] = f2tf(a1.x); As[nxt][ak + 9][ar] = f2tf(a1.y);
            As[nxt][ak +10][ar] = f2tf(a1.z); As[nxt][ak +11][ar] = f2tf(a1.w);
            float4 c0, c1;
            c0.x = f2tf(b0.x); c0.y = f2tf(b0.y); c0.z = f2tf(b0.z); c0.w = f2tf(b0.w);
            c1.x = f2tf(b1.x); c1.y = f2tf(b1.y); c1.z = f2tf(b1.z); c1.w = f2tf(b1.w);
            *(float4*)&Bs[nxt][bkr][bc]     = c0;
            *(float4*)&Bs[nxt][bkr + 8][bc] = c1;
        }
        __syncthreads();
    }

    // ---- epilogue ----
    #pragma unroll
    for (int mt = 0; mt < 4; mt++) {
        const int r0 = brow + wm + mt * 16 + gid;
        #pragma unroll
        for (int nt = 0; nt < 4; nt++) {
            const int c0 = bcol + wn + nt * 8 + tig * 2;
            float bx = bias[c0], by = bias[c0 + 1];
            float v00 = acc[mt][nt][0] + bx;
            float v01 = acc[mt][nt][1] + by;
            float v10 = acc[mt][nt][2] + bx;
            float v11 = acc[mt][nt][3] + by;
            if (EPI == 1) {
                v00 = 0.5f * v00 * (1.f + erff(v00 * 0.70710678118654752f));
                v01 = 0.5f * v01 * (1.f + erff(v01 * 0.70710678118654752f));
                v10 = 0.5f * v10 * (1.f + erff(v10 * 0.70710678118654752f));
                v11 = 0.5f * v11 * (1.f + erff(v11 * 0.70710678118654752f));
            } else if (EPI == 2) {
                float2 r0v = *(const float2*)&res[(size_t)r0 * N + c0];
                float2 r1v = *(const float2*)&res[(size_t)(r0 + 8) * N + c0];
                v00 += r0v.x; v01 += r0v.y; v10 += r1v.x; v11 += r1v.y;
            }
            float2 o0 = make_float2(v00, v01);
            float2 o1 = make_float2(v10, v11);
            *(float2*)&C[(size_t)r0 * N + c0]       = o0;
            *(float2*)&C[(size_t)(r0 + 8) * N + c0] = o1;
        }
    }
}

// ---------------- small guarded SGEMM (pool/classifier) ----------------
// EPI: 0 none, 1 gelu, 3 tanh
template<int EPI>
__global__ void gemm_kernel(const float* __restrict__ A, const float* __restrict__ W,
                            const float* __restrict__ bias,
                            float* __restrict__ C, int M, int N, int K) {
    __shared__ float As[16][65];
    __shared__ float Bs[16][64];
    const int brow = blockIdx.y * 64;
    const int bcol = blockIdx.x * 64;
    const int t  = threadIdx.x;
    const int ty = t >> 4, tx = t & 15;
    float acc[4][4] = {};
    for (int k0 = 0; k0 < K; k0 += 16) {
        #pragma unroll
        for (int l = t; l < 1024; l += 256) {
            int r = l >> 4, kk = l & 15;
            int gr = brow + r;
            As[kk][r] = (gr < M && k0 + kk < K) ? A[(size_t)gr * K + k0 + kk] : 0.f;
        }
        #pragma unroll
        for (int l = t; l < 1024; l += 256) {
            int kk = l >> 6, c = l & 63;
            int gc = bcol + c;
            Bs[kk][c] = (gc < N && k0 + kk < K) ? W[(size_t)(k0 + kk) * N + gc] : 0.f;
        }
        __syncthreads();
        #pragma unroll
        for (int kk = 0; kk < 16; kk++) {
            float a[4], bvals[4];
            #pragma unroll
            for (int i = 0; i < 4; i++) a[i] = As[kk][ty * 4 + i];
            #pragma unroll
            for (int j = 0; j < 4; j++) bvals[j] = Bs[kk][tx * 4 + j];
            #pragma unroll
            for (int i = 0; i < 4; i++)
                #pragma unroll
                for (int j = 0; j < 4; j++)
                    acc[i][j] += a[i] * bvals[j];
        }
        __syncthreads();
    }
    #pragma unroll
    for (int i = 0; i < 4; i++) {
        int row = brow + ty * 4 + i;
        if (row >= M) continue;
        #pragma unroll
        for (int j = 0; j < 4; j++) {
            int col = bcol + tx * 4 + j;
            if (col >= N) continue;
            float v = acc[i][j] + bias[col];
            if (EPI == 1) v = 0.5f * v * (1.f + erff(v * 0.70710678118654752f));
            else if (EPI == 3) v = tanhf(v);
            C[(size_t)row * N + col] = v;
        }
    }
}

// ---------------- fused attention ----------------
#define QT 128
#define KT 64

__global__ void attn_kernel(const float* __restrict__ q, const float* __restrict__ k,
                            const float* __restrict__ v, const float* __restrict__ rel,
                            const int* __restrict__ ids, float* __restrict__ out) {
    const int q0 = blockIdx.x * QT;
    const int h  = blockIdx.y;
    const int b  = blockIdx.z;
    const int ql = threadIdx.x;
    const int qg = q0 + ql;

    __shared__ float Ks[KT][NDK];
    __shared__ float Vs[KT][NDK];
    __shared__ float Rs[QT + KT - 1][NDK + 1];
    __shared__ int   Ms[KT];

    float qv[NDK];
    const float* qp = q + ((size_t)(b * NS + qg)) * ND + h * NDK;
    #pragma unroll
    for (int d = 0; d < NDK; d++) qv[d] = qp[d];

    float m = -INFINITY, l = 0.f;
    float acc[NDK];
    #pragma unroll
    for (int d = 0; d < NDK; d++) acc[d] = 0.f;
    const float scale = 0.17677669529663689f;

    for (int k0 = 0; k0 < NS; k0 += KT) {
        for (int idx = threadIdx.x; idx < KT * NDK; idx += QT) {
            int kk = idx >> 5, d = idx & 31;
            size_t off = ((size_t)(b * NS + k0 + kk)) * ND + h * NDK + d;
            Ks[kk][d] = k[off];
            Vs[kk][d] = v[off];
        }
        for (int idx = threadIdx.x; idx < (QT + KT - 1) * NDK; idx += QT) {
            int r = idx >> 5, d = idx & 31;
            int g = k0 - q0 + (NML - 1) - (QT - 1) + r;
            Rs[r][d] = rel[(size_t)g * NDK + d];
        }
        if (threadIdx.x < KT) Ms[threadIdx.x] = ids[b * NS + k0 + threadIdx.x];
        __syncthreads();

        for (int kk = 0; kk < KT; kk++) {
            const int rr = kk - ql + (QT - 1);
            float s = 0.f;
            #pragma unroll
            for (int d = 0; d < NDK; d++)
                s += qv[d] * (Ks[kk][d] + Rs[rr][d]);
            s *= scale;
            if (Ms[kk] != 0) {
                if (s <= m) {
                    float p = __expf(s - m);
                    l += p;
                    #pragma unroll
                    for (int d = 0; d < NDK; d++) acc[d] += p * Vs[kk][d];
                } else {
                    float c = __expf(m - s);
                    m = s;
                    l = l * c + 1.f;
                    #pragma unroll
                    for (int d = 0; d < NDK; d++) acc[d] = acc[d] * c + Vs[kk][d];
                }
            }
        }
        __syncthreads();
    }
    float inv = 1.f / l;
    float* op = out + ((size_t)(b * NS + qg)) * ND + h * NDK;
    #pragma unroll
    for (int d = 0; d < NDK; d++) op[d] = acc[d] * inv;
}

// ---------------- pooling ----------------
__global__ void pool_score_kernel(const float* __restrict__ tmp, const float* __restrict__ pw2,
                                  const float* __restrict__ pb2, float* __restrict__ scores) {
    int gid = blockIdx.x * (blockDim.x >> 5) + (threadIdx.x >> 5);
    if (gid >= 4 * NBS) return;
    int head = gid / NBS;
    int lane = threadIdx.x & 31;
    const float* p = tmp + (size_t)gid * 96;
    float s = 0.f;
    for (int j = lane; j < 96; j += 32) s += p[j] * pw2[head * 96 + j];
    #pragma unroll
    for (int o = 16; o > 0; o >>= 1) s += __shfl_xor_sync(0xffffffffu, s, o);
    if (lane == 0) scores[gid] = s + pb2[head];
}

__global__ void pool_kernel(const float* __restrict__ x, const float* __restrict__ scores,
                            const int* __restrict__ ids, float* __restrict__ pooled) {
    const int head = blockIdx.x;
    const int b    = blockIdx.y;
    __shared__ float ps[NS];
    __shared__ float red[8];
    const float* sc = scores + (size_t)head * NBS + (size_t)b * NS;

    float m = -INFINITY;
    for (int s = threadIdx.x; s < NS; s += 256) {
        float val = (ids[b * NS + s] == 0) ? -INFINITY : sc[s];
        ps[s] = val;
        m = fmaxf(m, val);
    }
    #pragma unroll
    for (int o = 16; o > 0; o >>= 1) m = fmaxf(m, __shfl_xor_sync(0xffffffffu, m, o));
    if ((threadIdx.x & 31) == 0) red[threadIdx.x >> 5] = m;
    __syncthreads();
    float M = -INFINITY;
    #pragma unroll
    for (int i = 0; i < 8; i++) M = fmaxf(M, red[i]);
    __syncthreads();

    float sum = 0.f;
    for (int s = threadIdx.x; s < NS; s += 256) {
        float p = __expf(ps[s] - M);
        ps[s] = p;
        sum += p;
    }
    #pragma unroll
    for (int o = 16; o > 0; o >>= 1) sum += __shfl_xor_sync(0xffffffffu, sum, o);
    if ((threadIdx.x & 31) == 0) red[threadIdx.x >> 5] = sum;
    __syncthreads();
    float T = 0.f;
    #pragma unroll
    for (int i = 0; i < 8; i++) T += red[i];
    __syncthreads();
    float inv = 1.f / T;

    for (int d = threadIdx.x; d < ND; d += 256) {
        float acc = 0.f;
        const float* xp = x + (size_t)b * NS * ND + d;
        for (int s = 0; s < NS; s++) acc += ps[s] * xp[(size_t)s * ND];
        pooled[(size_t)b * (4 * ND) + head * ND + d] = acc * inv;
    }
}

// ---------------- dispatchers ----------------
static void run_big_gemm(const float* A, const float* W, const float* bias, const float* res,
                         float* C, int M, int N, int K, int epi) {
    dim3 grid(N / 128, M / 128);
    switch (epi) {
        case 0: gemm_tc_kernel<0><<<grid, 256>>>(A, W, bias, res, C, M, N, K); break;
        case 1: gemm_tc_kernel<1><<<grid, 256>>>(A, W, bias, res, C, M, N, K); break;
        case 2: gemm_tc_kernel<2><<<grid, 256>>>(A, W, bias, res, C, M, N, K); break;
    }
}

static void run_small_gemm(const float* A, const float* W, const float* bias,
                           float* C, int M, int N, int K, int epi) {
    dim3 grid((N + 63) / 64, (M + 63) / 64);
    switch (epi) {
        case 0: gemm_kernel<0><<<grid, 256>>>(A, W, bias, C, M, N, K); break;
        case 1: gemm_kernel<1><<<grid, 256>>>(A, W, bias, C, M, N, K); break;
        case 3: gemm_kernel<3><<<grid, 256>>>(A, W, bias, C, M, N, K); break;
    }
}

// ---------------- entry ----------------
extern "C" void kernel_launch(void* const* d_in, const int* in_sizes, int n_in,
                              void* d_out, int out_size) {
    const float* te   = (const float*)d_in[0];
    const float* pe   = (const float*)d_in[1];
    const float* wq   = (const float*)d_in[2];
    const float* bq   = (const float*)d_in[3];
    const float* wk   = (const float*)d_in[4];
    const float* bk   = (const float*)d_in[5];
    const float* wv   = (const float*)d_in[6];
    const float* bv   = (const float*)d_in[7];
    const float* wo   = (const float*)d_in[8];
    const float* bo   = (const float*)d_in[9];
    const float* rel  = (const float*)d_in[10];
    const float* g1   = (const float*)d_in[11];
    const float* b1   = (const float*)d_in[12];
    const float* g2   = (const float*)d_in[13];
    const float* b2   = (const float*)d_in[14];
    const float* fw1  = (const float*)d_in[15];
    const float* fb1  = (const float*)d_in[16];
    const float* fw2  = (const float*)d_in[17];
    const float* fb2  = (const float*)d_in[18];
    const float* fg   = (const float*)d_in[19];
    const float* fbn  = (const float*)d_in[20];
    const float* pw1  = (const float*)d_in[21];
    const float* pb1  = (const float*)d_in[22];
    const float* pw2  = (const float*)d_in[23];
    const float* pb2  = (const float*)d_in[24];
    const float* cw1  = (const float*)d_in[25];
    const float* cb1  = (const float*)d_in[26];
    const float* cw2  = (const float*)d_in[27];
    const float* cb2  = (const float*)d_in[28];
    const float* cw3  = (const float*)d_in[29];
    const float* cb3  = (const float*)d_in[30];
    const int*   ids  = (const int*)d_in[31];

    float* S;
    cudaGetSymbolAddress((void**)&S, g_scratch);
    float* X  = S + OFF_X;
    float* HB = S + OFF_H;
    float* Q  = S + OFF_Q;
    float* K  = S + OFF_K;
    float* V  = S + OFF_V;
    float* AB = S + OFF_A;
    float* FB = S + OFF_FF;
    float* PT = S + OFF_PT;
    float* PS = S + OFF_PS;
    float* PD = S + OFF_PD;
    float* C1 = S + OFF_C1;
    float* C2 = S + OFF_C2;

    embed_kernel<<<NBS, ND>>>(te, pe, ids, X);

    for (int l = 0; l < NL; l++) {
        const size_t wOff = (size_t)l * ND * ND;
        const size_t dOff = (size_t)l * ND;
        ln_kernel<<<NBS, 128>>>(X, HB, g1 + dOff, b1 + dOff);
        run_big_gemm(HB, wq + wOff, bq + dOff, nullptr, Q, NBS, ND, ND, 0);
        run_big_gemm(HB, wk + wOff, bk + dOff, nullptr, K, NBS, ND, ND, 0);
        run_big_gemm(HB, wv + wOff, bv + dOff, nullptr, V, NBS, ND, ND, 0);
        attn_kernel<<<dim3(NS / QT, NH, NB), QT>>>(
            Q, K, V, rel + (size_t)l * (2 * NML - 1) * NDK, ids, AB);
        run_big_gemm(AB, wo + wOff, bo + dOff, X, X, NBS, ND, ND, 2);
        ln_kernel<<<NBS, 128>>>(X, HB, g2 + dOff, b2 + dOff);
        run_big_gemm(HB, fw1 + (size_t)l * ND * NFF, fb1 + (size_t)l * NFF, nullptr, FB,
                     NBS, NFF, ND, 1);
        run_big_gemm(FB, fw2 + (size_t)l * NFF * ND, fb2 + dOff, X, X, NBS, ND, NFF, 2);
    }

    ln_kernel<<<NBS, 128>>>(X, HB, fg, fbn);

    for (int i = 0; i < 4; i++)
        run_small_gemm(HB, pw1 + (size_t)i * ND * 96, pb1 + (size_t)i * 96,
                       PT + (size_t)i * NBS * 96, NBS, 96, ND, 3);
    pool_score_kernel<<<(4 * NBS + 3) / 4, 128>>>(PT, pw2, pb2, PS);
    pool_kernel<<<dim3(4, NB), 256>>>(HB, PS, ids, PD);

    run_small_gemm(PD, cw1, cb1, C1, NB, ND, 4 * ND, 1);
    run_small_gemm(C1, cw2, cb2, C2, NB, 192, ND, 1);
    run_small_gemm(C2, cw3, cb3, (float*)d_out, NB, NNC, 192, 0);
}

// round 4
// speedup vs baseline: 3.0759x; 1.5874x over previous
#include <cuda_runtime.h>
#include <math.h>
#include <stdint.h>

// ---------------- problem dims ----------------
#define NB   16
#define NS   768
#define ND   384
#define NH   12
#define NDK  32
#define NFF  1024
#define NL   6
#define NML  768
#define NNC  10
#define NBS  (NB*NS)          // 12288 rows

// ---------------- scratch ----------------
#define OFF_X   ((size_t)0)
#define OFF_H   (OFF_X  + (size_t)NBS*ND)
#define OFF_Q   (OFF_H  + (size_t)NBS*ND)
#define OFF_K   (OFF_Q  + (size_t)NBS*ND)
#define OFF_V   (OFF_K  + (size_t)NBS*ND)
#define OFF_A   (OFF_V  + (size_t)NBS*ND)
#define OFF_FF  (OFF_A  + (size_t)NBS*ND)
#define OFF_PT  (OFF_FF + (size_t)NBS*NFF)
#define OFF_PS  (OFF_PT + (size_t)4*NBS*96)
#define OFF_PD  (OFF_PS + (size_t)4*NBS)
#define OFF_C1  (OFF_PD + (size_t)NB*4*ND)
#define OFF_C2  (OFF_C1 + (size_t)NB*ND)
#define SCRATCH_TOTAL (OFF_C2 + (size_t)NB*192)

static __device__ float g_scratch[SCRATCH_TOTAL];

// ---------------- tf32 helpers ----------------
__device__ __forceinline__ float f2tf(float f) {
    uint32_t u;
    asm("cvt.rna.tf32.f32 %0, %1;" : "=r"(u) : "f"(f));
    return __uint_as_float(u);
}

__device__ __forceinline__ void mma_tf32(float* c, const float* a, const float* b) {
    asm volatile(
        "mma.sync.aligned.m16n8k8.row.col.f32.tf32.tf32.f32 "
        "{%0,%1,%2,%3}, {%4,%5,%6,%7}, {%8,%9}, {%0,%1,%2,%3};"
        : "+f"(c[0]), "+f"(c[1]), "+f"(c[2]), "+f"(c[3])
        : "r"(__float_as_uint(a[0])), "r"(__float_as_uint(a[1])),
          "r"(__float_as_uint(a[2])), "r"(__float_as_uint(a[3])),
          "r"(__float_as_uint(b[0])), "r"(__float_as_uint(b[1])));
}

// ---------------- embed ----------------
__global__ void embed_kernel(const float* __restrict__ te, const float* __restrict__ pe,
                             const int* __restrict__ ids, float* __restrict__ x) {
    int row = blockIdx.x;
    int d   = threadIdx.x;
    int s   = row % NS;
    int id  = ids[row];
    x[(size_t)row * ND + d] = te[(size_t)id * ND + d] + pe[(size_t)s * ND + d];
}

// ---------------- layernorm (float4, 128 thr/row) ----------------
__device__ __forceinline__ float block_sum128(float v, float* red) {
    #pragma unroll
    for (int o = 16; o > 0; o >>= 1) v += __shfl_xor_sync(0xffffffffu, v, o);
    int w = threadIdx.x >> 5;
    if ((threadIdx.x & 31) == 0) red[w] = v;
    __syncthreads();
    float t = red[0] + red[1] + red[2] + red[3];
    __syncthreads();
    return t;
}

__global__ void ln_kernel(const float* __restrict__ in, float* __restrict__ out,
                          const float* __restrict__ g, const float* __restrict__ b) {
    __shared__ float red[4];
    int row = blockIdx.x;
    const float4* p = (const float4*)(in + (size_t)row * ND);
    int i = threadIdx.x;
    float4 v4 = (i < 96) ? p[i] : make_float4(0.f, 0.f, 0.f, 0.f);
    float s = v4.x + v4.y + v4.z + v4.w;
    float mean = block_sum128(s, red) * (1.f / ND);
    float vs = 0.f;
    if (i < 96) {
        float a = v4.x - mean, bb = v4.y - mean, c = v4.z - mean, d = v4.w - mean;
        vs = a * a + bb * bb + c * c + d * d;
    }
    float var = block_sum128(vs, red) * (1.f / ND);
    float inv = rsqrtf(var + 1e-5f);
    if (i < 96) {
        float4 gv = ((const float4*)g)[i];
        float4 bv = ((const float4*)b)[i];
        float4 o;
        o.x = (v4.x - mean) * inv * gv.x + bv.x;
        o.y = (v4.y - mean) * inv * gv.y + bv.y;
        o.z = (v4.z - mean) * inv * gv.z + bv.z;
        o.w = (v4.w - mean) * inv * gv.w + bv.w;
        ((float4*)(out + (size_t)row * ND))[i] = o;
    }
}

// ================= tf32 tensor-core GEMM: 128x128 tile, BK=16 =================
#define GSTRIDE 136

template<int EPI>
__global__ void __launch_bounds__(256, 2)
gemm_tc_kernel(const float* __restrict__ A, const float* __restrict__ W,
               const float* __restrict__ bias, const float* __restrict__ res,
               float* __restrict__ C, int M, int N, int K) {
    __shared__ float As[2][16][GSTRIDE];
    __shared__ float Bs[2][16][GSTRIDE];

    const int t    = threadIdx.x;
    const int lane = t & 31;
    const int warp = t >> 5;
    const int wm   = (warp & 1) * 64;
    const int wn   = (warp >> 1) * 32;
    const int gid  = lane >> 2;
    const int tig  = lane & 3;
    const int brow = blockIdx.y * 128;
    const int bcol = blockIdx.x * 128;

    const int ar = t & 127;
    const int ak = (t >> 7) * 4;
    const int bkr = t >> 5;
    const int bc  = lane * 4;

    const float* Ap = A + (size_t)(brow + ar) * K;

    float acc[4][4][4];
    #pragma unroll
    for (int i = 0; i < 4; i++)
        #pragma unroll
        for (int j = 0; j < 4; j++)
            #pragma unroll
            for (int r = 0; r < 4; r++) acc[i][j][r] = 0.f;

    const int ntiles = K / 16;

    {
        float4 a0 = *(const float4*)&Ap[ak];
        float4 a1 = *(const float4*)&Ap[ak + 8];
        float4 b0 = *(const float4*)&W[(size_t)bkr * N + bcol + bc];
        float4 b1 = *(const float4*)&W[(size_t)(bkr + 8) * N + bcol + bc];
        As[0][ak + 0][ar] = f2tf(a0.x); As[0][ak + 1][ar] = f2tf(a0.y);
        As[0][ak + 2][ar] = f2tf(a0.z); As[0][ak + 3][ar] = f2tf(a0.w);
        As[0][ak + 8][ar] = f2tf(a1.x); As[0][ak + 9][ar] = f2tf(a1.y);
        As[0][ak +10][ar] = f2tf(a1.z); As[0][ak +11][ar] = f2tf(a1.w);
        float4 c0, c1;
        c0.x = f2tf(b0.x); c0.y = f2tf(b0.y); c0.z = f2tf(b0.z); c0.w = f2tf(b0.w);
        c1.x = f2tf(b1.x); c1.y = f2tf(b1.y); c1.z = f2tf(b1.z); c1.w = f2tf(b1.w);
        *(float4*)&Bs[0][bkr][bc]     = c0;
        *(float4*)&Bs[0][bkr + 8][bc] = c1;
    }
    __syncthreads();

    for (int tt = 0; tt < ntiles; tt++) {
        const int cur = tt & 1;
        const int nxt = cur ^ 1;
        const bool more = (tt + 1 < ntiles);
        float4 a0, a1, b0, b1;
        if (more) {
            const int k0 = (tt + 1) * 16;
            a0 = *(const float4*)&Ap[k0 + ak];
            a1 = *(const float4*)&Ap[k0 + ak + 8];
            b0 = *(const float4*)&W[(size_t)(k0 + bkr) * N + bcol + bc];
            b1 = *(const float4*)&W[(size_t)(k0 + bkr + 8) * N + bcol + bc];
        }
        #pragma unroll
        for (int ks = 0; ks < 2; ks++) {
            const int kb = ks * 8;
            float a[4][4], b[4][2];
            #pragma unroll
            for (int mt = 0; mt < 4; mt++) {
                const int m0 = wm + mt * 16 + gid;
                a[mt][0] = As[cur][kb + tig][m0];
                a[mt][1] = As[cur][kb + tig][m0 + 8];
                a[mt][2] = As[cur][kb + tig + 4][m0];
                a[mt][3] = As[cur][kb + tig + 4][m0 + 8];
            }
            #pragma unroll
            for (int nt = 0; nt < 4; nt++) {
                const int n0 = wn + nt * 8 + gid;
                b[nt][0] = Bs[cur][kb + tig][n0];
                b[nt][1] = Bs[cur][kb + tig + 4][n0];
            }
            #pragma unroll
            for (int mt = 0; mt < 4; mt++)
                #pragma unroll
                for (int nt = 0; nt < 4; nt++)
                    mma_tf32(acc[mt][nt], a[mt], b[nt]);
        }
        if (more) {
            As[nxt][ak + 0][ar] = f2tf(a0.x); As[nxt][ak + 1][ar] = f2tf(a0.y);
            As[nxt][ak + 2][ar] = f2tf(a0.z); As[nxt][ak + 3][ar] = f2tf(a0.w);
            As[nxt][ak + 8][ar] = f2tf(a1.x); As[nxt][ak + 9][ar] = f2tf(a1.y);
            As[nxt][ak +10][ar] = f2tf(a1.z); As[nxt][ak +11][ar] = f2tf(a1.w);
            float4 c0, c1;
            c0.x = f2tf(b0.x); c0.y = f2tf(b0.y); c0.z = f2tf(b0.z); c0.w = f2tf(b0.w);
            c1.x = f2tf(b1.x); c1.y = f2tf(b1.y); c1.z = f2tf(b1.z); c1.w = f2tf(b1.w);
            *(float4*)&Bs[nxt][bkr][bc]     = c0;
            *(float4*)&Bs[nxt][bkr + 8][bc] = c1;
        }
        __syncthreads();
    }

    #pragma unroll
    for (int mt = 0; mt < 4; mt++) {
        const int r0 = brow + wm + mt * 16 + gid;
        #pragma unroll
        for (int nt = 0; nt < 4; nt++) {
            const int c0 = bcol + wn + nt * 8 + tig * 2;
            float bx = bias[c0], by = bias[c0 + 1];
            float v00 = acc[mt][nt][0] + bx;
            float v01 = acc[mt][nt][1] + by;
            float v10 = acc[mt][nt][2] + bx;
            float v11 = acc[mt][nt][3] + by;
            if (EPI == 1) {
                v00 = 0.5f * v00 * (1.f + erff(v00 * 0.70710678118654752f));
                v01 = 0.5f * v01 * (1.f + erff(v01 * 0.70710678118654752f));
                v10 = 0.5f * v10 * (1.f + erff(v10 * 0.70710678118654752f));
                v11 = 0.5f * v11 * (1.f + erff(v11 * 0.70710678118654752f));
            } else if (EPI == 2) {
                float2 r0v = *(const float2*)&res[(size_t)r0 * N + c0];
                float2 r1v = *(const float2*)&res[(size_t)(r0 + 8) * N + c0];
                v00 += r0v.x; v01 += r0v.y; v10 += r1v.x; v11 += r1v.y;
            }
            *(float2*)&C[(size_t)r0 * N + c0]       = make_float2(v00, v01);
            *(float2*)&C[(size_t)(r0 + 8) * N + c0] = make_float2(v10, v11);
        }
    }
}

// ---------------- small guarded SGEMM (pool/classifier) ----------------
template<int EPI>
__global__ void gemm_kernel(const float* __restrict__ A, const float* __restrict__ W,
                            const float* __restrict__ bias,
                            float* __restrict__ C, int M, int N, int K) {
    __shared__ float As[16][65];
    __shared__ float Bs[16][64];
    const int brow = blockIdx.y * 64;
    const int bcol = blockIdx.x * 64;
    const int t  = threadIdx.x;
    const int ty = t >> 4, tx = t & 15;
    float acc[4][4] = {};
    for (int k0 = 0; k0 < K; k0 += 16) {
        #pragma unroll
        for (int l = t; l < 1024; l += 256) {
            int r = l >> 4, kk = l & 15;
            int gr = brow + r;
            As[kk][r] = (gr < M && k0 + kk < K) ? A[(size_t)gr * K + k0 + kk] : 0.f;
        }
        #pragma unroll
        for (int l = t; l < 1024; l += 256) {
            int kk = l >> 6, c = l & 63;
            int gc = bcol + c;
            Bs[kk][c] = (gc < N && k0 + kk < K) ? W[(size_t)(k0 + kk) * N + gc] : 0.f;
        }
        __syncthreads();
        #pragma unroll
        for (int kk = 0; kk < 16; kk++) {
            float a[4], bvals[4];
            #pragma unroll
            for (int i = 0; i < 4; i++) a[i] = As[kk][ty * 4 + i];
            #pragma unroll
            for (int j = 0; j < 4; j++) bvals[j] = Bs[kk][tx * 4 + j];
            #pragma unroll
            for (int i = 0; i < 4; i++)
                #pragma unroll
                for (int j = 0; j < 4; j++)
                    acc[i][j] += a[i] * bvals[j];
        }
        __syncthreads();
    }
    #pragma unroll
    for (int i = 0; i < 4; i++) {
        int row = brow + ty * 4 + i;
        if (row >= M) continue;
        #pragma unroll
        for (int j = 0; j < 4; j++) {
            int col = bcol + tx * 4 + j;
            if (col >= N) continue;
            float v = acc[i][j] + bias[col];
            if (EPI == 1) v = 0.5f * v * (1.f + erff(v * 0.70710678118654752f));
            else if (EPI == 3) v = tanhf(v);
            C[(size_t)row * N + col] = v;
        }
    }
}

// ================= tensor-core flash attention with banded rel bias =================
// grid (6 q-tiles, 12 heads, 16 batch); 256 threads = 8 warps; warp w owns q rows
// [q0+16w, q0+16w+16). Per 64-key tile: rel-band MMA (per-warp 80-wide band) ->
// smem stage -> QK MMA -> combine along shifted diagonal -> online softmax -> PV MMA.
// smem layout (floats): Qs[32][132] | Ks[32][68] | Rs[32][200] | Vs[64][36] |
//                       WS[8][16][84] | Mk[64] (int)
#define ATT_SMEM_WORDS 25920
#define ATT_SMEM_BYTES (ATT_SMEM_WORDS * 4)

__global__ void __launch_bounds__(256)
attn_tc_kernel(const float* __restrict__ q, const float* __restrict__ k,
               const float* __restrict__ v, const float* __restrict__ rel,
               const int* __restrict__ ids, float* __restrict__ out) {
    extern __shared__ float sm[];
    float* Qs = sm;                   // [32][132] (d-major, transposed)
    float* Ks = sm + 4224;            // [32][68]
    float* Rs = sm + 6400;            // [32][200]
    float* Vs = sm + 12800;           // [64][36]
    float* WS = sm + 15104;           // [8][16][84]
    int*   Mk = (int*)(sm + 25856);   // [64]

    const int q0 = blockIdx.x * 128;
    const int h  = blockIdx.y;
    const int b  = blockIdx.z;
    const int t    = threadIdx.x;
    const int lane = t & 31;
    const int w    = t >> 5;
    const int gid  = lane >> 2;
    const int tig  = lane & 3;
    float* WSw = WS + w * (16 * 84);
    const int j0w = 112 - 16 * w;     // warp band offset into block rel band
    const float scale = 0.17677669529663689f;

    // ---- load Q tile (transposed, tf32) ----
    {
        const float* qb = q + ((size_t)(b * NS + q0)) * ND + h * NDK;
        #pragma unroll
        for (int i = t; i < 1024; i += 256) {
            int r = i >> 3, d0 = (i & 7) * 4;
            float4 x = *(const float4*)&qb[(size_t)r * ND + d0];
            Qs[(d0 + 0) * 132 + r] = f2tf(x.x);
            Qs[(d0 + 1) * 132 + r] = f2tf(x.y);
            Qs[(d0 + 2) * 132 + r] = f2tf(x.z);
            Qs[(d0 + 3) * 132 + r] = f2tf(x.w);
        }
    }

    float m_lo = -INFINITY, m_hi = -INFINITY, l_lo = 0.f, l_hi = 0.f;
    float oa[4][4];
    #pragma unroll
    for (int i = 0; i < 4; i++)
        #pragma unroll
        for (int j = 0; j < 4; j++) oa[i][j] = 0.f;

    for (int k0 = 0; k0 < NS; k0 += 64) {
        __syncthreads();
        // ---- load K (transposed) and V (row-major) tiles ----
        {
            const float* kb = k + ((size_t)(b * NS + k0)) * ND + h * NDK;
            const float* vb = v + ((size_t)(b * NS + k0)) * ND + h * NDK;
            #pragma unroll
            for (int i = t; i < 512; i += 256) {
                int r = i >> 3, d0 = (i & 7) * 4;
                float4 x = *(const float4*)&kb[(size_t)r * ND + d0];
                Ks[(d0 + 0) * 68 + r] = f2tf(x.x);
                Ks[(d0 + 1) * 68 + r] = f2tf(x.y);
                Ks[(d0 + 2) * 68 + r] = f2tf(x.z);
                Ks[(d0 + 3) * 68 + r] = f2tf(x.w);
                float4 y = *(const float4*)&vb[(size_t)r * ND + d0];
                float4 z;
                z.x = f2tf(y.x); z.y = f2tf(y.y); z.z = f2tf(y.z); z.w = f2tf(y.w);
                *(float4*)&Vs[r * 36 + d0] = z;
            }
            // rel band rows: delta = k0 - q0 + 640 + j, j in [0,191)
            const float* rb = rel + (size_t)(k0 - q0 + 640) * NDK;
            for (int i = t; i < 191 * 8; i += 256) {
                int j = i >> 3, d0 = (i & 7) * 4;
                float4 x = *(const float4*)&rb[(size_t)j * NDK + d0];
                Rs[(d0 + 0) * 200 + j] = f2tf(x.x);
                Rs[(d0 + 1) * 200 + j] = f2tf(x.y);
                Rs[(d0 + 2) * 200 + j] = f2tf(x.z);
                Rs[(d0 + 3) * 200 + j] = f2tf(x.w);
            }
            if (t < 64) Mk[t] = ids[b * NS + k0 + t];
        }
        __syncthreads();

        // ---- A fragments (Q) shared by rel & QK MMAs ----
        float af[4][4];
        #pragma unroll
        for (int ks = 0; ks < 4; ks++) {
            int kk = ks * 8 + tig;
            int m0 = w * 16 + gid;
            af[ks][0] = Qs[kk * 132 + m0];
            af[ks][1] = Qs[kk * 132 + m0 + 8];
            af[ks][2] = Qs[(kk + 4) * 132 + m0];
            af[ks][3] = Qs[(kk + 4) * 132 + m0 + 8];
        }

        // ---- rel-band MMA: P[16 x 80] ----
        {
            float rc[10][4];
            #pragma unroll
            for (int nt = 0; nt < 10; nt++)
                #pragma unroll
                for (int e = 0; e < 4; e++) rc[nt][e] = 0.f;
            #pragma unroll
            for (int ks = 0; ks < 4; ks++) {
                int kk = ks * 8 + tig;
                #pragma unroll
                for (int nt = 0; nt < 10; nt++) {
                    int col = j0w + nt * 8 + gid;
                    float bb[2];
                    bb[0] = Rs[kk * 200 + col];
                    bb[1] = Rs[(kk + 4) * 200 + col];
                    mma_tf32(rc[nt], af[ks], bb);
                }
            }
            #pragma unroll
            for (int nt = 0; nt < 10; nt++) {
                int c0 = nt * 8 + 2 * tig;
                WSw[gid * 84 + c0]           = rc[nt][0];
                WSw[gid * 84 + c0 + 1]       = rc[nt][1];
                WSw[(gid + 8) * 84 + c0]     = rc[nt][2];
                WSw[(gid + 8) * 84 + c0 + 1] = rc[nt][3];
            }
        }
        __syncwarp();

        // ---- QK MMA: S1[16 x 64] ----
        float qa[8][4];
        #pragma unroll
        for (int nt = 0; nt < 8; nt++)
            #pragma unroll
            for (int e = 0; e < 4; e++) qa[nt][e] = 0.f;
        #pragma unroll
        for (int ks = 0; ks < 4; ks++) {
            int kk = ks * 8 + tig;
            #pragma unroll
            for (int nt = 0; nt < 8; nt++) {
                int col = nt * 8 + gid;
                float bb[2];
                bb[0] = Ks[kk * 68 + col];
                bb[1] = Ks[(kk + 4) * 68 + col];
                mma_tf32(qa[nt], af[ks], bb);
            }
        }

        // ---- combine: S = scale*(S1 + band[r][k+15-r]), mask ----
        #pragma unroll
        for (int nt = 0; nt < 8; nt++) {
            int kl0 = nt * 8 + 2 * tig;
            int kl1 = kl0 + 1;
            int rlo = gid, rhi = gid + 8;
            bool m0b = (Mk[kl0] == 0), m1b = (Mk[kl1] == 0);
            qa[nt][0] = m0b ? -INFINITY : (qa[nt][0] + WSw[rlo * 84 + kl0 + 15 - rlo]) * scale;
            qa[nt][1] = m1b ? -INFINITY : (qa[nt][1] + WSw[rlo * 84 + kl1 + 15 - rlo]) * scale;
            qa[nt][2] = m0b ? -INFINITY : (qa[nt][2] + WSw[rhi * 84 + kl0 + 15 - rhi]) * scale;
            qa[nt][3] = m1b ? -INFINITY : (qa[nt][3] + WSw[rhi * 84 + kl1 + 15 - rhi]) * scale;
        }
        __syncwarp();

        // ---- online softmax (per-row stats live in each quad) ----
        float tm_lo = -INFINITY, tm_hi = -INFINITY;
        #pragma unroll
        for (int nt = 0; nt < 8; nt++) {
            tm_lo = fmaxf(tm_lo, fmaxf(qa[nt][0], qa[nt][1]));
            tm_hi = fmaxf(tm_hi, fmaxf(qa[nt][2], qa[nt][3]));
        }
        tm_lo = fmaxf(tm_lo, __shfl_xor_sync(0xffffffffu, tm_lo, 1));
        tm_lo = fmaxf(tm_lo, __shfl_xor_sync(0xffffffffu, tm_lo, 2));
        tm_hi = fmaxf(tm_hi, __shfl_xor_sync(0xffffffffu, tm_hi, 1));
        tm_hi = fmaxf(tm_hi, __shfl_xor_sync(0xffffffffu, tm_hi, 2));

        float nm_lo = fmaxf(m_lo, tm_lo);
        float nm_hi = fmaxf(m_hi, tm_hi);
        float c_lo = 1.f, c_hi = 1.f, sum_lo = 0.f, sum_hi = 0.f;

        if (nm_lo == -INFINITY) {
            #pragma unroll
            for (int nt = 0; nt < 8; nt++) {
                int c0 = nt * 8 + 2 * tig;
                WSw[gid * 84 + c0] = 0.f; WSw[gid * 84 + c0 + 1] = 0.f;
            }
        } else {
            c_lo = __expf(m_lo - nm_lo);
            #pragma unroll
            for (int nt = 0; nt < 8; nt++) {
                int c0 = nt * 8 + 2 * tig;
                float p0 = __expf(qa[nt][0] - nm_lo);
                float p1 = __expf(qa[nt][1] - nm_lo);
                sum_lo += p0 + p1;
                WSw[gid * 84 + c0]     = f2tf(p0);
                WSw[gid * 84 + c0 + 1] = f2tf(p1);
            }
        }
        if (nm_hi == -INFINITY) {
            #pragma unroll
            for (int nt = 0; nt < 8; nt++) {
                int c0 = nt * 8 + 2 * tig;
                WSw[(gid + 8) * 84 + c0] = 0.f; WSw[(gid + 8) * 84 + c0 + 1] = 0.f;
            }
        } else {
            c_hi = __expf(m_hi - nm_hi);
            #pragma unroll
            for (int nt = 0; nt < 8; nt++) {
                int c0 = nt * 8 + 2 * tig;
                float p0 = __expf(qa[nt][2] - nm_hi);
                float p1 = __expf(qa[nt][3] - nm_hi);
                sum_hi += p0 + p1;
                WSw[(gid + 8) * 84 + c0]     = f2tf(p0);
                WSw[(gid + 8) * 84 + c0 + 1] = f2tf(p1);
            }
        }
        sum_lo += __shfl_xor_sync(0xffffffffu, sum_lo, 1);
        sum_lo += __shfl_xor_sync(0xffffffffu, sum_lo, 2);
        sum_hi += __shfl_xor_sync(0xffffffffu, sum_hi, 1);
        sum_hi += __shfl_xor_sync(0xffffffffu, sum_hi, 2);
        m_lo = nm_lo; m_hi = nm_hi;
        l_lo = l_lo * c_lo + sum_lo;
        l_hi = l_hi * c_hi + sum_hi;
        #pragma unroll
        for (int nt = 0; nt < 4; nt++) {
            oa[nt][0] *= c_lo; oa[nt][1] *= c_lo;
            oa[nt][2] *= c_hi; oa[nt][3] *= c_hi;
        }
        __syncwarp();

        // ---- PV MMA: O[16 x 32] += P[16 x 64] @ V[64 x 32] ----
        #pragma unroll
        for (int ks = 0; ks < 8; ks++) {
            int kk = ks * 8 + tig;
            float pa[4];
            pa[0] = WSw[gid * 84 + kk];
            pa[1] = WSw[(gid + 8) * 84 + kk];
            pa[2] = WSw[gid * 84 + kk + 4];
            pa[3] = WSw[(gid + 8) * 84 + kk + 4];
            #pragma unroll
            for (int nt = 0; nt < 4; nt++) {
                int col = nt * 8 + gid;
                float bb[2];
                bb[0] = Vs[kk * 36 + col];
                bb[1] = Vs[(kk + 4) * 36 + col];
                mma_tf32(oa[nt], pa, bb);
            }
        }
    }

    // ---- finalize ----
    float inv_lo = (l_lo > 0.f) ? 1.f / l_lo : 0.f;
    float inv_hi = (l_hi > 0.f) ? 1.f / l_hi : 0.f;
    const int rlo = b * NS + q0 + w * 16 + gid;
    #pragma unroll
    for (int nt = 0; nt < 4; nt++) {
        int col = h * NDK + nt * 8 + 2 * tig;
        out[(size_t)rlo * ND + col]           = oa[nt][0] * inv_lo;
        out[(size_t)rlo * ND + col + 1]       = oa[nt][1] * inv_lo;
        out[(size_t)(rlo + 8) * ND + col]     = oa[nt][2] * inv_hi;
        out[(size_t)(rlo + 8) * ND + col + 1] = oa[nt][3] * inv_hi;
    }
}

// ---------------- pooling ----------------
__global__ void pool_score_kernel(const float* __restrict__ tmp, const float* __restrict__ pw2,
                                  const float* __restrict__ pb2, float* __restrict__ scores) {
    int gid = blockIdx.x * (blockDim.x >> 5) + (threadIdx.x >> 5);
    if (gid >= 4 * NBS) return;
    int head = gid / NBS;
    int lane = threadIdx.x & 31;
    const float* p = tmp + (size_t)gid * 96;
    float s = 0.f;
    for (int j = lane; j < 96; j += 32) s += p[j] * pw2[head * 96 + j];
    #pragma unroll
    for (int o = 16; o > 0; o >>= 1) s += __shfl_xor_sync(0xffffffffu, s, o);
    if (lane == 0) scores[gid] = s + pb2[head];
}

__global__ void pool_kernel(const float* __restrict__ x, const float* __restrict__ scores,
                            const int* __restrict__ ids, float* __restrict__ pooled) {
    const int head = blockIdx.x;
    const int b    = blockIdx.y;
    __shared__ float ps[NS];
    __shared__ float red[8];
    const float* sc = scores + (size_t)head * NBS + (size_t)b * NS;

    float m = -INFINITY;
    for (int s = threadIdx.x; s < NS; s += 256) {
        float val = (ids[b * NS + s] == 0) ? -INFINITY : sc[s];
        ps[s] = val;
        m = fmaxf(m, val);
    }
    #pragma unroll
    for (int o = 16; o > 0; o >>= 1) m = fmaxf(m, __shfl_xor_sync(0xffffffffu, m, o));
    if ((threadIdx.x & 31) == 0) red[threadIdx.x >> 5] = m;
    __syncthreads();
    float M = -INFINITY;
    #pragma unroll
    for (int i = 0; i < 8; i++) M = fmaxf(M, red[i]);
    __syncthreads();

    float sum = 0.f;
    for (int s = threadIdx.x; s < NS; s += 256) {
        float p = __expf(ps[s] - M);
        ps[s] = p;
        sum += p;
    }
    #pragma unroll
    for (int o = 16; o > 0; o >>= 1) sum += __shfl_xor_sync(0xffffffffu, sum, o);
    if ((threadIdx.x & 31) == 0) red[threadIdx.x >> 5] = sum;
    __syncthreads();
    float T = 0.f;
    #pragma unroll
    for (int i = 0; i < 8; i++) T += red[i];
    __syncthreads();
    float inv = 1.f / T;

    for (int d = threadIdx.x; d < ND; d += 256) {
        float acc = 0.f;
        const float* xp = x + (size_t)b * NS * ND + d;
        for (int s = 0; s < NS; s++) acc += ps[s] * xp[(size_t)s * ND];
        pooled[(size_t)b * (4 * ND) + head * ND + d] = acc * inv;
    }
}

// ---------------- dispatchers ----------------
static void run_big_gemm(const float* A, const float* W, const float* bias, const float* res,
                         float* C, int M, int N, int K, int epi) {
    dim3 grid(N / 128, M / 128);
    switch (epi) {
        case 0: gemm_tc_kernel<0><<<grid, 256>>>(A, W, bias, res, C, M, N, K); break;
        case 1: gemm_tc_kernel<1><<<grid, 256>>>(A, W, bias, res, C, M, N, K); break;
        case 2: gemm_tc_kernel<2><<<grid, 256>>>(A, W, bias, res, C, M, N, K); break;
    }
}

static void run_small_gemm(const float* A, const float* W, const float* bias,
                           float* C, int M, int N, int K, int epi) {
    dim3 grid((N + 63) / 64, (M + 63) / 64);
    switch (epi) {
        case 0: gemm_kernel<0><<<grid, 256>>>(A, W, bias, C, M, N, K); break;
        case 1: gemm_kernel<1><<<grid, 256>>>(A, W, bias, C, M, N, K); break;
        case 3: gemm_kernel<3><<<grid, 256>>>(A, W, bias, C, M, N, K); break;
    }
}

// ---------------- entry ----------------
extern "C" void kernel_launch(void* const* d_in, const int* in_sizes, int n_in,
                              void* d_out, int out_size) {
    const float* te   = (const float*)d_in[0];
    const float* pe   = (const float*)d_in[1];
    const float* wq   = (const float*)d_in[2];
    const float* bq   = (const float*)d_in[3];
    const float* wk   = (const float*)d_in[4];
    const float* bk   = (const float*)d_in[5];
    const float* wv   = (const float*)d_in[6];
    const float* bv   = (const float*)d_in[7];
    const float* wo   = (const float*)d_in[8];
    const float* bo   = (const float*)d_in[9];
    const float* rel  = (const float*)d_in[10];
    const float* g1   = (const float*)d_in[11];
    const float* b1   = (const float*)d_in[12];
    const float* g2   = (const float*)d_in[13];
    const float* b2   = (const float*)d_in[14];
    const float* fw1  = (const float*)d_in[15];
    const float* fb1  = (const float*)d_in[16];
    const float* fw2  = (const float*)d_in[17];
    const float* fb2  = (const float*)d_in[18];
    const float* fg   = (const float*)d_in[19];
    const float* fbn  = (const float*)d_in[20];
    const float* pw1  = (const float*)d_in[21];
    const float* pb1  = (const float*)d_in[22];
    const float* pw2  = (const float*)d_in[23];
    const float* pb2  = (const float*)d_in[24];
    const float* cw1  = (const float*)d_in[25];
    const float* cb1  = (const float*)d_in[26];
    const float* cw2  = (const float*)d_in[27];
    const float* cb2  = (const float*)d_in[28];
    const float* cw3  = (const float*)d_in[29];
    const float* cb3  = (const float*)d_in[30];
    const int*   ids  = (const int*)d_in[31];

    float* S;
    cudaGetSymbolAddress((void**)&S, g_scratch);
    float* X  = S + OFF_X;
    float* HB = S + OFF_H;
    float* Q  = S + OFF_Q;
    float* K  = S + OFF_K;
    float* V  = S + OFF_V;
    float* AB = S + OFF_A;
    float* FB = S + OFF_FF;
    float* PT = S + OFF_PT;
    float* PS = S + OFF_PS;
    float* PD = S + OFF_PD;
    float* C1 = S + OFF_C1;
    float* C2 = S + OFF_C2;

    static bool attr_set = false;
    if (!attr_set) {
        cudaFuncSetAttribute(attn_tc_kernel,
                             cudaFuncAttributeMaxDynamicSharedMemorySize, ATT_SMEM_BYTES);
        attr_set = true;
    }

    embed_kernel<<<NBS, ND>>>(te, pe, ids, X);

    for (int l = 0; l < NL; l++) {
        const size_t wOff = (size_t)l * ND * ND;
        const size_t dOff = (size_t)l * ND;
        ln_kernel<<<NBS, 128>>>(X, HB, g1 + dOff, b1 + dOff);
        run_big_gemm(HB, wq + wOff, bq + dOff, nullptr, Q, NBS, ND, ND, 0);
        run_big_gemm(HB, wk + wOff, bk + dOff, nullptr, K, NBS, ND, ND, 0);
        run_big_gemm(HB, wv + wOff, bv + dOff, nullptr, V, NBS, ND, ND, 0);
        attn_tc_kernel<<<dim3(NS / 128, NH, NB), 256, ATT_SMEM_BYTES>>>(
            Q, K, V, rel + (size_t)l * (2 * NML - 1) * NDK, ids, AB);
        run_big_gemm(AB, wo + wOff, bo + dOff, X, X, NBS, ND, ND, 2);
        ln_kernel<<<NBS, 128>>>(X, HB, g2 + dOff, b2 + dOff);
        run_big_gemm(HB, fw1 + (size_t)l * ND * NFF, fb1 + (size_t)l * NFF, nullptr, FB,
                     NBS, NFF, ND, 1);
        run_big_gemm(FB, fw2 + (size_t)l * NFF * ND, fb2 + dOff, X, X, NBS, ND, NFF, 2);
    }

    ln_kernel<<<NBS, 128>>>(X, HB, fg, fbn);

    for (int i = 0; i < 4; i++)
        run_small_gemm(HB, pw1 + (size_t)i * ND * 96, pb1 + (size_t)i * 96,
                       PT + (size_t)i * NBS * 96, NBS, 96, ND, 3);
    pool_score_kernel<<<(4 * NBS + 3) / 4, 128>>>(PT, pw2, pb2, PS);
    pool_kernel<<<dim3(4, NB), 256>>>(HB, PS, ids, PD);

    run_small_gemm(PD, cw1, cb1, C1, NB, ND, 4 * ND, 1);
    run_small_gemm(C1, cw2, cb2, C2, NB, 192, ND, 1);
    run_small_gemm(C2, cw3, cb3, (float*)d_out, NB, NNC, 192, 0);
}

// round 5
// speedup vs baseline: 3.1628x; 1.0282x over previous
#include <cuda_runtime.h>
#include <math.h>
#include <stdint.h>

// ---------------- problem dims ----------------
#define NB   16
#define NS   768
#define ND   384
#define NH   12
#define NDK  32
#define NFF  1024
#define NL   6
#define NML  768
#define NNC  10
#define NBS  (NB*NS)          // 12288 rows

// ---------------- scratch ----------------
#define OFF_X   ((size_t)0)
#define OFF_H   (OFF_X  + (size_t)NBS*ND)
#define OFF_Q   (OFF_H  + (size_t)NBS*ND)
#define OFF_K   (OFF_Q  + (size_t)NBS*ND)
#define OFF_V   (OFF_K  + (size_t)NBS*ND)
#define OFF_A   (OFF_V  + (size_t)NBS*ND)
#define OFF_FF  (OFF_A  + (size_t)NBS*ND)
#define OFF_PT  (OFF_FF + (size_t)NBS*NFF)
#define OFF_PS  (OFF_PT + (size_t)4*NBS*96)
#define OFF_PD  (OFF_PS + (size_t)4*NBS)
#define OFF_C1  (OFF_PD + (size_t)NB*4*ND)
#define OFF_C2  (OFF_C1 + (size_t)NB*ND)
#define SCRATCH_TOTAL (OFF_C2 + (size_t)NB*192)

static __device__ float g_scratch[SCRATCH_TOTAL];

// ---------------- tf32 helpers ----------------
__device__ __forceinline__ float f2tf(float f) {
    uint32_t u;
    asm("cvt.rna.tf32.f32 %0, %1;" : "=r"(u) : "f"(f));
    return __uint_as_float(u);
}

__device__ __forceinline__ void mma_tf32(float* c, const float* a, const float* b) {
    asm volatile(
        "mma.sync.aligned.m16n8k8.row.col.f32.tf32.tf32.f32 "
        "{%0,%1,%2,%3}, {%4,%5,%6,%7}, {%8,%9}, {%0,%1,%2,%3};"
        : "+f"(c[0]), "+f"(c[1]), "+f"(c[2]), "+f"(c[3])
        : "r"(__float_as_uint(a[0])), "r"(__float_as_uint(a[1])),
          "r"(__float_as_uint(a[2])), "r"(__float_as_uint(a[3])),
          "r"(__float_as_uint(b[0])), "r"(__float_as_uint(b[1])));
}

// ---------------- embed ----------------
__global__ void embed_kernel(const float* __restrict__ te, const float* __restrict__ pe,
                             const int* __restrict__ ids, float* __restrict__ x) {
    int row = blockIdx.x;
    int d   = threadIdx.x;
    int s   = row % NS;
    int id  = ids[row];
    x[(size_t)row * ND + d] = te[(size_t)id * ND + d] + pe[(size_t)s * ND + d];
}

// ---------------- layernorm (float4, 128 thr/row) ----------------
__device__ __forceinline__ float block_sum128(float v, float* red) {
    #pragma unroll
    for (int o = 16; o > 0; o >>= 1) v += __shfl_xor_sync(0xffffffffu, v, o);
    int w = threadIdx.x >> 5;
    if ((threadIdx.x & 31) == 0) red[w] = v;
    __syncthreads();
    float t = red[0] + red[1] + red[2] + red[3];
    __syncthreads();
    return t;
}

__global__ void ln_kernel(const float* __restrict__ in, float* __restrict__ out,
                          const float* __restrict__ g, const float* __restrict__ b) {
    __shared__ float red[4];
    int row = blockIdx.x;
    const float4* p = (const float4*)(in + (size_t)row * ND);
    int i = threadIdx.x;
    float4 v4 = (i < 96) ? p[i] : make_float4(0.f, 0.f, 0.f, 0.f);
    float s = v4.x + v4.y + v4.z + v4.w;
    float mean = block_sum128(s, red) * (1.f / ND);
    float vs = 0.f;
    if (i < 96) {
        float a = v4.x - mean, bb = v4.y - mean, c = v4.z - mean, d = v4.w - mean;
        vs = a * a + bb * bb + c * c + d * d;
    }
    float var = block_sum128(vs, red) * (1.f / ND);
    float inv = rsqrtf(var + 1e-5f);
    if (i < 96) {
        float4 gv = ((const float4*)g)[i];
        float4 bv = ((const float4*)b)[i];
        float4 o;
        o.x = (v4.x - mean) * inv * gv.x + bv.x;
        o.y = (v4.y - mean) * inv * gv.y + bv.y;
        o.z = (v4.z - mean) * inv * gv.z + bv.z;
        o.w = (v4.w - mean) * inv * gv.w + bv.w;
        ((float4*)(out + (size_t)row * ND))[i] = o;
    }
}

// ================= tf32 tensor-core GEMM: 128x128 tile, BK=16 =================
// A smem is fragment-major: one LDS.128 per warp A-fragment.
//  addr(k<16, m<128) = (k>>3)*1024 + (m>>4)*128 + (m&7)*16
//                      + ((k&3) ^ (((m&7)>>1)&3))*4 + ((k>>2)&1)*2 + ((m>>3)&1)
#define GSTRIDE 136

template<int EPI>
__global__ void __launch_bounds__(256, 2)
gemm_tc_kernel(const float* __restrict__ A, const float* __restrict__ W,
               const float* __restrict__ bias, const float* __restrict__ res,
               float* __restrict__ C, int M, int N, int K) {
    __shared__ __align__(16) float As2[2][2048];
    __shared__ float Bs[2][16][GSTRIDE];

    const int t    = threadIdx.x;
    const int lane = t & 31;
    const int warp = t >> 5;
    const int wm   = (warp & 1) * 64;
    const int wn   = (warp >> 1) * 32;
    const int gid  = lane >> 2;
    const int tig  = lane & 3;
    const int brow = blockIdx.y * 128;
    const int bcol = blockIdx.x * 128;

    // A loader mapping
    const int ar    = t & 127;            // A row
    const int aksel = t >> 7;             // 0/1 -> k quads {0-3,8-11} vs {4-7,12-15}
    const int ak    = aksel * 4;
    const int agid  = ar & 7;
    const int amb   = (ar >> 4) * 128 + agid * 16 + aksel * 2 + ((ar >> 3) & 1);
    const int asw   = (agid >> 1) & 3;    // store-side xor swizzle
    // B loader mapping
    const int bkr = t >> 5;
    const int bc  = lane * 4;

    // fragment read offsets
    const int swt   = ((tig ^ ((gid >> 1) & 3)) << 2);
    const int afrag = (wm >> 4) * 128 + gid * 16 + swt;   // + mt*128 + ks*1024

    const float* Ap = A + (size_t)(brow + ar) * K;

    float acc[4][4][4];
    #pragma unroll
    for (int i = 0; i < 4; i++)
        #pragma unroll
        for (int j = 0; j < 4; j++)
            #pragma unroll
            for (int r = 0; r < 4; r++) acc[i][j][r] = 0.f;

    const int ntiles = K / 16;

    // ---- prologue: tile 0 -> buf 0 ----
    {
        float4 a0 = *(const float4*)&Ap[ak];
        float4 a1 = *(const float4*)&Ap[ak + 8];
        const float* av0 = &a0.x;
        const float* av1 = &a1.x;
        #pragma unroll
        for (int j = 0; j < 4; j++) {
            int off = ((j ^ asw) << 2);
            As2[0][amb + off]        = f2tf(av0[j]);
            As2[0][1024 + amb + off] = f2tf(av1[j]);
        }
        float4 b0 = *(const float4*)&W[(size_t)bkr * N + bcol + bc];
        float4 b1 = *(const float4*)&W[(size_t)(bkr + 8) * N + bcol + bc];
        float4 c0, c1;
        c0.x = f2tf(b0.x); c0.y = f2tf(b0.y); c0.z = f2tf(b0.z); c0.w = f2tf(b0.w);
        c1.x = f2tf(b1.x); c1.y = f2tf(b1.y); c1.z = f2tf(b1.z); c1.w = f2tf(b1.w);
        *(float4*)&Bs[0][bkr][bc]     = c0;
        *(float4*)&Bs[0][bkr + 8][bc] = c1;
    }
    __syncthreads();

    for (int tt = 0; tt < ntiles; tt++) {
        const int cur = tt & 1;
        const int nxt = cur ^ 1;
        const bool more = (tt + 1 < ntiles);
        float4 a0, a1, b0, b1;
        if (more) {
            const int k0 = (tt + 1) * 16;
            a0 = *(const float4*)&Ap[k0 + ak];
            a1 = *(const float4*)&Ap[k0 + ak + 8];
            b0 = *(const float4*)&W[(size_t)(k0 + bkr) * N + bcol + bc];
            b1 = *(const float4*)&W[(size_t)(k0 + bkr + 8) * N + bcol + bc];
        }
        #pragma unroll
        for (int ks = 0; ks < 2; ks++) {
            const int kb = ks * 8;
            float a[4][4], b[4][2];
            #pragma unroll
            for (int mt = 0; mt < 4; mt++) {
                float4 av = *(const float4*)&As2[cur][ks * 1024 + mt * 128 + afrag];
                a[mt][0] = av.x; a[mt][1] = av.y; a[mt][2] = av.z; a[mt][3] = av.w;
            }
            #pragma unroll
            for (int nt = 0; nt < 4; nt++) {
                const int n0 = wn + nt * 8 + gid;
                b[nt][0] = Bs[cur][kb + tig][n0];
                b[nt][1] = Bs[cur][kb + tig + 4][n0];
            }
            #pragma unroll
            for (int mt = 0; mt < 4; mt++)
                #pragma unroll
                for (int nt = 0; nt < 4; nt++)
                    mma_tf32(acc[mt][nt], a[mt], b[nt]);
        }
        if (more) {
            const float* av0 = &a0.x;
            const float* av1 = &a1.x;
            #pragma unroll
            for (int j = 0; j < 4; j++) {
                int off = ((j ^ asw) << 2);
                As2[nxt][amb + off]        = f2tf(av0[j]);
                As2[nxt][1024 + amb + off] = f2tf(av1[j]);
            }
            float4 c0, c1;
            c0.x = f2tf(b0.x); c0.y = f2tf(b0.y); c0.z = f2tf(b0.z); c0.w = f2tf(b0.w);
            c1.x = f2tf(b1.x); c1.y = f2tf(b1.y); c1.z = f2tf(b1.z); c1.w = f2tf(b1.w);
            *(float4*)&Bs[nxt][bkr][bc]     = c0;
            *(float4*)&Bs[nxt][bkr + 8][bc] = c1;
        }
        __syncthreads();
    }

    // ---- epilogue ----
    #pragma unroll
    for (int mt = 0; mt < 4; mt++) {
        const int r0 = brow + wm + mt * 16 + gid;
        #pragma unroll
        for (int nt = 0; nt < 4; nt++) {
            const int c0 = bcol + wn + nt * 8 + tig * 2;
            float bx = bias[c0], by = bias[c0 + 1];
            float v00 = acc[mt][nt][0] + bx;
            float v01 = acc[mt][nt][1] + by;
            float v10 = acc[mt][nt][2] + bx;
            float v11 = acc[mt][nt][3] + by;
            if (EPI == 1) {
                v00 = 0.5f * v00 * (1.f + erff(v00 * 0.70710678118654752f));
                v01 = 0.5f * v01 * (1.f + erff(v01 * 0.70710678118654752f));
                v10 = 0.5f * v10 * (1.f + erff(v10 * 0.70710678118654752f));
                v11 = 0.5f * v11 * (1.f + erff(v11 * 0.70710678118654752f));
            } else if (EPI == 2) {
                float2 r0v = *(const float2*)&res[(size_t)r0 * N + c0];
                float2 r1v = *(const float2*)&res[(size_t)(r0 + 8) * N + c0];
                v00 += r0v.x; v01 += r0v.y; v10 += r1v.x; v11 += r1v.y;
            }
            *(float2*)&C[(size_t)r0 * N + c0]       = make_float2(v00, v01);
            *(float2*)&C[(size_t)(r0 + 8) * N + c0] = make_float2(v10, v11);
        }
    }
}

// ---------------- small guarded SGEMM (pool/classifier) ----------------
template<int EPI>
__global__ void gemm_kernel(const float* __restrict__ A, const float* __restrict__ W,
                            const float* __restrict__ bias,
                            float* __restrict__ C, int M, int N, int K) {
    __shared__ float As[16][65];
    __shared__ float Bs[16][64];
    const int brow = blockIdx.y * 64;
    const int bcol = blockIdx.x * 64;
    const int t  = threadIdx.x;
    const int ty = t >> 4, tx = t & 15;
    float acc[4][4] = {};
    for (int k0 = 0; k0 < K; k0 += 16) {
        #pragma unroll
        for (int l = t; l < 1024; l += 256) {
            int r = l >> 4, kk = l & 15;
            int gr = brow + r;
            As[kk][r] = (gr < M && k0 + kk < K) ? A[(size_t)gr * K + k0 + kk] : 0.f;
        }
        #pragma unroll
        for (int l = t; l < 1024; l += 256) {
            int kk = l >> 6, c = l & 63;
            int gc = bcol + c;
            Bs[kk][c] = (gc < N && k0 + kk < K) ? W[(size_t)(k0 + kk) * N + gc] : 0.f;
        }
        __syncthreads();
        #pragma unroll
        for (int kk = 0; kk < 16; kk++) {
            float a[4], bvals[4];
            #pragma unroll
            for (int i = 0; i < 4; i++) a[i] = As[kk][ty * 4 + i];
            #pragma unroll
            for (int j = 0; j < 4; j++) bvals[j] = Bs[kk][tx * 4 + j];
            #pragma unroll
            for (int i = 0; i < 4; i++)
                #pragma unroll
                for (int j = 0; j < 4; j++)
                    acc[i][j] += a[i] * bvals[j];
        }
        __syncthreads();
    }
    #pragma unroll
    for (int i = 0; i < 4; i++) {
        int row = brow + ty * 4 + i;
        if (row >= M) continue;
        #pragma unroll
        for (int j = 0; j < 4; j++) {
            int col = bcol + tx * 4 + j;
            if (col >= N) continue;
            float v = acc[i][j] + bias[col];
            if (EPI == 1) v = 0.5f * v * (1.f + erff(v * 0.70710678118654752f));
            else if (EPI == 3) v = tanhf(v);
            C[(size_t)row * N + col] = v;
        }
    }
}

// ================= tensor-core flash attention with banded rel bias =================
#define ATT_SMEM_WORDS 25920
#define ATT_SMEM_BYTES (ATT_SMEM_WORDS * 4)

__global__ void __launch_bounds__(256)
attn_tc_kernel(const float* __restrict__ q, const float* __restrict__ k,
               const float* __restrict__ v, const float* __restrict__ rel,
               const int* __restrict__ ids, float* __restrict__ out) {
    extern __shared__ float sm[];
    float* Qs = sm;                   // [32][132] (d-major, transposed)
    float* Ks = sm + 4224;            // [32][68]
    float* Rs = sm + 6400;            // [32][200]
    float* Vs = sm + 12800;           // [64][36]
    float* WS = sm + 15104;           // [8][16][84]
    int*   Mk = (int*)(sm + 25856);   // [64]

    const int q0 = blockIdx.x * 128;
    const int h  = blockIdx.y;
    const int b  = blockIdx.z;
    const int t    = threadIdx.x;
    const int lane = t & 31;
    const int w    = t >> 5;
    const int gid  = lane >> 2;
    const int tig  = lane & 3;
    float* WSw = WS + w * (16 * 84);
    const int j0w = 112 - 16 * w;     // warp band offset into block rel band
    const float scale = 0.17677669529663689f;

    // ---- load Q tile (transposed, tf32) ----
    {
        const float* qb = q + ((size_t)(b * NS + q0)) * ND + h * NDK;
        #pragma unroll
        for (int i = t; i < 1024; i += 256) {
            int r = i >> 3, d0 = (i & 7) * 4;
            float4 x = *(const float4*)&qb[(size_t)r * ND + d0];
            Qs[(d0 + 0) * 132 + r] = f2tf(x.x);
            Qs[(d0 + 1) * 132 + r] = f2tf(x.y);
            Qs[(d0 + 2) * 132 + r] = f2tf(x.z);
            Qs[(d0 + 3) * 132 + r] = f2tf(x.w);
        }
    }
    __syncthreads();

    // ---- Q fragments: loaded ONCE (independent of k-tile) ----
    float af[4][4];
    #pragma unroll
    for (int ks = 0; ks < 4; ks++) {
        int kk = ks * 8 + tig;
        int m0 = w * 16 + gid;
        af[ks][0] = Qs[kk * 132 + m0];
        af[ks][1] = Qs[kk * 132 + m0 + 8];
        af[ks][2] = Qs[(kk + 4) * 132 + m0];
        af[ks][3] = Qs[(kk + 4) * 132 + m0 + 8];
    }

    float m_lo = -INFINITY, m_hi = -INFINITY, l_lo = 0.f, l_hi = 0.f;
    float oa[4][4];
    #pragma unroll
    for (int i = 0; i < 4; i++)
        #pragma unroll
        for (int j = 0; j < 4; j++) oa[i][j] = 0.f;

    for (int k0 = 0; k0 < NS; k0 += 64) {
        __syncthreads();
        // ---- load K (transposed) and V (row-major) tiles ----
        {
            const float* kb = k + ((size_t)(b * NS + k0)) * ND + h * NDK;
            const float* vb = v + ((size_t)(b * NS + k0)) * ND + h * NDK;
            #pragma unroll
            for (int i = t; i < 512; i += 256) {
                int r = i >> 3, d0 = (i & 7) * 4;
                float4 x = *(const float4*)&kb[(size_t)r * ND + d0];
                Ks[(d0 + 0) * 68 + r] = f2tf(x.x);
                Ks[(d0 + 1) * 68 + r] = f2tf(x.y);
                Ks[(d0 + 2) * 68 + r] = f2tf(x.z);
                Ks[(d0 + 3) * 68 + r] = f2tf(x.w);
                float4 y = *(const float4*)&vb[(size_t)r * ND + d0];
                float4 z;
                z.x = f2tf(y.x); z.y = f2tf(y.y); z.z = f2tf(y.z); z.w = f2tf(y.w);
                *(float4*)&Vs[r * 36 + d0] = z;
            }
            // rel band rows: delta = k0 - q0 + 640 + j, j in [0,191)
            const float* rb = rel + (size_t)(k0 - q0 + 640) * NDK;
            for (int i = t; i < 191 * 8; i += 256) {
                int j = i >> 3, d0 = (i & 7) * 4;
                float4 x = *(const float4*)&rb[(size_t)j * NDK + d0];
                Rs[(d0 + 0) * 200 + j] = f2tf(x.x);
                Rs[(d0 + 1) * 200 + j] = f2tf(x.y);
                Rs[(d0 + 2) * 200 + j] = f2tf(x.z);
                Rs[(d0 + 3) * 200 + j] = f2tf(x.w);
            }
            if (t < 64) Mk[t] = ids[b * NS + k0 + t];
        }
        __syncthreads();

        // ---- rel-band MMA: P[16 x 80] ----
        {
            float rc[10][4];
            #pragma unroll
            for (int nt = 0; nt < 10; nt++)
                #pragma unroll
                for (int e = 0; e < 4; e++) rc[nt][e] = 0.f;
            #pragma unroll
            for (int ks = 0; ks < 4; ks++) {
                int kk = ks * 8 + tig;
                #pragma unroll
                for (int nt = 0; nt < 10; nt++) {
                    int col = j0w + nt * 8 + gid;
                    float bb[2];
                    bb[0] = Rs[kk * 200 + col];
                    bb[1] = Rs[(kk + 4) * 200 + col];
                    mma_tf32(rc[nt], af[ks], bb);
                }
            }
            #pragma unroll
            for (int nt = 0; nt < 10; nt++) {
                int c0 = nt * 8 + 2 * tig;
                WSw[gid * 84 + c0]           = rc[nt][0];
                WSw[gid * 84 + c0 + 1]       = rc[nt][1];
                WSw[(gid + 8) * 84 + c0]     = rc[nt][2];
                WSw[(gid + 8) * 84 + c0 + 1] = rc[nt][3];
            }
        }
        __syncwarp();

        // ---- QK MMA: S1[16 x 64] ----
        float qa[8][4];
        #pragma unroll
        for (int nt = 0; nt < 8; nt++)
            #pragma unroll
            for (int e = 0; e < 4; e++) qa[nt][e] = 0.f;
        #pragma unroll
        for (int ks = 0; ks < 4; ks++) {
            int kk = ks * 8 + tig;
            #pragma unroll
            for (int nt = 0; nt < 8; nt++) {
                int col = nt * 8 + gid;
                float bb[2];
                bb[0] = Ks[kk * 68 + col];
                bb[1] = Ks[(kk + 4) * 68 + col];
                mma_tf32(qa[nt], af[ks], bb);
            }
        }

        // ---- combine: S = scale*(S1 + band[r][k+15-r]), mask ----
        #pragma unroll
        for (int nt = 0; nt < 8; nt++) {
            int kl0 = nt * 8 + 2 * tig;
            int kl1 = kl0 + 1;
            int rlo = gid, rhi = gid + 8;
            bool m0b = (Mk[kl0] == 0), m1b = (Mk[kl1] == 0);
            qa[nt][0] = m0b ? -INFINITY : (qa[nt][0] + WSw[rlo * 84 + kl0 + 15 - rlo]) * scale;
            qa[nt][1] = m1b ? -INFINITY : (qa[nt][1] + WSw[rlo * 84 + kl1 + 15 - rlo]) * scale;
            qa[nt][2] = m0b ? -INFINITY : (qa[nt][2] + WSw[rhi * 84 + kl0 + 15 - rhi]) * scale;
            qa[nt][3] = m1b ? -INFINITY : (qa[nt][3] + WSw[rhi * 84 + kl1 + 15 - rhi]) * scale;
        }
        __syncwarp();

        // ---- online softmax ----
        float tm_lo = -INFINITY, tm_hi = -INFINITY;
        #pragma unroll
        for (int nt = 0; nt < 8; nt++) {
            tm_lo = fmaxf(tm_lo, fmaxf(qa[nt][0], qa[nt][1]));
            tm_hi = fmaxf(tm_hi, fmaxf(qa[nt][2], qa[nt][3]));
        }
        tm_lo = fmaxf(tm_lo, __shfl_xor_sync(0xffffffffu, tm_lo, 1));
        tm_lo = fmaxf(tm_lo, __shfl_xor_sync(0xffffffffu, tm_lo, 2));
        tm_hi = fmaxf(tm_hi, __shfl_xor_sync(0xffffffffu, tm_hi, 1));
        tm_hi = fmaxf(tm_hi, __shfl_xor_sync(0xffffffffu, tm_hi, 2));

        float nm_lo = fmaxf(m_lo, tm_lo);
        float nm_hi = fmaxf(m_hi, tm_hi);
        float c_lo = 1.f, c_hi = 1.f, sum_lo = 0.f, sum_hi = 0.f;

        if (nm_lo == -INFINITY) {
            #pragma unroll
            for (int nt = 0; nt < 8; nt++) {
                int c0 = nt * 8 + 2 * tig;
                WSw[gid * 84 + c0] = 0.f; WSw[gid * 84 + c0 + 1] = 0.f;
            }
        } else {
            c_lo = __expf(m_lo - nm_lo);
            #pragma unroll
            for (int nt = 0; nt < 8; nt++) {
                int c0 = nt * 8 + 2 * tig;
                float p0 = __expf(qa[nt][0] - nm_lo);
                float p1 = __expf(qa[nt][1] - nm_lo);
                sum_lo += p0 + p1;
                WSw[gid * 84 + c0]     = f2tf(p0);
                WSw[gid * 84 + c0 + 1] = f2tf(p1);
            }
        }
        if (nm_hi == -INFINITY) {
            #pragma unroll
            for (int nt = 0; nt < 8; nt++) {
                int c0 = nt * 8 + 2 * tig;
                WSw[(gid + 8) * 84 + c0] = 0.f; WSw[(gid + 8) * 84 + c0 + 1] = 0.f;
            }
        } else {
            c_hi = __expf(m_hi - nm_hi);
            #pragma unroll
            for (int nt = 0; nt < 8; nt++) {
                int c0 = nt * 8 + 2 * tig;
                float p0 = __expf(qa[nt][2] - nm_hi);
                float p1 = __expf(qa[nt][3] - nm_hi);
                sum_hi += p0 + p1;
                WSw[(gid + 8) * 84 + c0]     = f2tf(p0);
                WSw[(gid + 8) * 84 + c0 + 1] = f2tf(p1);
            }
        }
        sum_lo += __shfl_xor_sync(0xffffffffu, sum_lo, 1);
        sum_lo += __shfl_xor_sync(0xffffffffu, sum_lo, 2);
        sum_hi += __shfl_xor_sync(0xffffffffu, sum_hi, 1);
        sum_hi += __shfl_xor_sync(0xffffffffu, sum_hi, 2);
        m_lo = nm_lo; m_hi = nm_hi;
        l_lo = l_lo * c_lo + sum_lo;
        l_hi = l_hi * c_hi + sum_hi;
        #pragma unroll
        for (int nt = 0; nt < 4; nt++) {
            oa[nt][0] *= c_lo; oa[nt][1] *= c_lo;
            oa[nt][2] *= c_hi; oa[nt][3] *= c_hi;
        }
        __syncwarp();

        // ---- PV MMA: O[16 x 32] += P[16 x 64] @ V[64 x 32] ----
        #pragma unroll
        for (int ks = 0; ks < 8; ks++) {
            int kk = ks * 8 + tig;
            float pa[4];
            pa[0] = WSw[gid * 84 + kk];
            pa[1] = WSw[(gid + 8) * 84 + kk];
            pa[2] = WSw[gid * 84 + kk + 4];
            pa[3] = WSw[(gid + 8) * 84 + kk + 4];
            #pragma unroll
            for (int nt = 0; nt < 4; nt++) {
                int col = nt * 8 + gid;
                float bb[2];
                bb[0] = Vs[kk * 36 + col];
                bb[1] = Vs[(kk + 4) * 36 + col];
                mma_tf32(oa[nt], pa, bb);
            }
        }
    }

    // ---- finalize ----
    float inv_lo = (l_lo > 0.f) ? 1.f / l_lo : 0.f;
    float inv_hi = (l_hi > 0.f) ? 1.f / l_hi : 0.f;
    const int rlo = b * NS + q0 + w * 16 + gid;
    #pragma unroll
    for (int nt = 0; nt < 4; nt++) {
        int col = h * NDK + nt * 8 + 2 * tig;
        out[(size_t)rlo * ND + col]           = oa[nt][0] * inv_lo;
        out[(size_t)rlo * ND + col + 1]       = oa[nt][1] * inv_lo;
        out[(size_t)(rlo + 8) * ND + col]     = oa[nt][2] * inv_hi;
        out[(size_t)(rlo + 8) * ND + col + 1] = oa[nt][3] * inv_hi;
    }
}

// ---------------- pooling ----------------
__global__ void pool_score_kernel(const float* __restrict__ tmp, const float* __restrict__ pw2,
                                  const float* __restrict__ pb2, float* __restrict__ scores) {
    int gid = blockIdx.x * (blockDim.x >> 5) + (threadIdx.x >> 5);
    if (gid >= 4 * NBS) return;
    int head = gid / NBS;
    int lane = threadIdx.x & 31;
    const float* p = tmp + (size_t)gid * 96;
    float s = 0.f;
    for (int j = lane; j < 96; j += 32) s += p[j] * pw2[head * 96 + j];
    #pragma unroll
    for (int o = 16; o > 0; o >>= 1) s += __shfl_xor_sync(0xffffffffu, s, o);
    if (lane == 0) scores[gid] = s + pb2[head];
}

__global__ void pool_kernel(const float* __restrict__ x, const float* __restrict__ scores,
                            const int* __restrict__ ids, float* __restrict__ pooled) {
    const int head = blockIdx.x;
    const int b    = blockIdx.y;
    __shared__ float ps[NS];
    __shared__ float red[8];
    const float* sc = scores + (size_t)head * NBS + (size_t)b * NS;

    float m = -INFINITY;
    for (int s = threadIdx.x; s < NS; s += 256) {
        float val = (ids[b * NS + s] == 0) ? -INFINITY : sc[s];
        ps[s] = val;
        m = fmaxf(m, val);
    }
    #pragma unroll
    for (int o = 16; o > 0; o >>= 1) m = fmaxf(m, __shfl_xor_sync(0xffffffffu, m, o));
    if ((threadIdx.x & 31) == 0) red[threadIdx.x >> 5] = m;
    __syncthreads();
    float M = -INFINITY;
    #pragma unroll
    for (int i = 0; i < 8; i++) M = fmaxf(M, red[i]);
    __syncthreads();

    float sum = 0.f;
    for (int s = threadIdx.x; s < NS; s += 256) {
        float p = __expf(ps[s] - M);
        ps[s] = p;
        sum += p;
    }
    #pragma unroll
    for (int o = 16; o > 0; o >>= 1) sum += __shfl_xor_sync(0xffffffffu, sum, o);
    if ((threadIdx.x & 31) == 0) red[threadIdx.x >> 5] = sum;
    __syncthreads();
    float T = 0.f;
    #pragma unroll
    for (int i = 0; i < 8; i++) T += red[i];
    __syncthreads();
    float inv = 1.f / T;

    for (int d = threadIdx.x; d < ND; d += 256) {
        float acc = 0.f;
        const float* xp = x + (size_t)b * NS * ND + d;
        for (int s = 0; s < NS; s++) acc += ps[s] * xp[(size_t)s * ND];
        pooled[(size_t)b * (4 * ND) + head * ND + d] = acc * inv;
    }
}

// ---------------- dispatchers ----------------
static void run_big_gemm(const float* A, const float* W, const float* bias, const float* res,
                         float* C, int M, int N, int K, int epi) {
    dim3 grid(N / 128, M / 128);
    switch (epi) {
        case 0: gemm_tc_kernel<0><<<grid, 256>>>(A, W, bias, res, C, M, N, K); break;
        case 1: gemm_tc_kernel<1><<<grid, 256>>>(A, W, bias, res, C, M, N, K); break;
        case 2: gemm_tc_kernel<2><<<grid, 256>>>(A, W, bias, res, C, M, N, K); break;
    }
}

static void run_small_gemm(const float* A, const float* W, const float* bias,
                           float* C, int M, int N, int K, int epi) {
    dim3 grid((N + 63) / 64, (M + 63) / 64);
    switch (epi) {
        case 0: gemm_kernel<0><<<grid, 256>>>(A, W, bias, C, M, N, K); break;
        case 1: gemm_kernel<1><<<grid, 256>>>(A, W, bias, C, M, N, K); break;
        case 3: gemm_kernel<3><<<grid, 256>>>(A, W, bias, C, M, N, K); break;
    }
}

// ---------------- entry ----------------
extern "C" void kernel_launch(void* const* d_in, const int* in_sizes, int n_in,
                              void* d_out, int out_size) {
    const float* te   = (const float*)d_in[0];
    const float* pe   = (const float*)d_in[1];
    const float* wq   = (const float*)d_in[2];
    const float* bq   = (const float*)d_in[3];
    const float* wk   = (const float*)d_in[4];
    const float* bk   = (const float*)d_in[5];
    const float* wv   = (const float*)d_in[6];
    const float* bv   = (const float*)d_in[7];
    const float* wo   = (const float*)d_in[8];
    const float* bo   = (const float*)d_in[9];
    const float* rel  = (const float*)d_in[10];
    const float* g1   = (const float*)d_in[11];
    const float* b1   = (const float*)d_in[12];
    const float* g2   = (const float*)d_in[13];
    const float* b2   = (const float*)d_in[14];
    const float* fw1  = (const float*)d_in[15];
    const float* fb1  = (const float*)d_in[16];
    const float* fw2  = (const float*)d_in[17];
    const float* fb2  = (const float*)d_in[18];
    const float* fg   = (const float*)d_in[19];
    const float* fbn  = (const float*)d_in[20];
    const float* pw1  = (const float*)d_in[21];
    const float* pb1  = (const float*)d_in[22];
    const float* pw2  = (const float*)d_in[23];
    const float* pb2  = (const float*)d_in[24];
    const float* cw1  = (const float*)d_in[25];
    const float* cb1  = (const float*)d_in[26];
    const float* cw2  = (const float*)d_in[27];
    const float* cb2  = (const float*)d_in[28];
    const float* cw3  = (const float*)d_in[29];
    const float* cb3  = (const float*)d_in[30];
    const int*   ids  = (const int*)d_in[31];

    float* S;
    cudaGetSymbolAddress((void**)&S, g_scratch);
    float* X  = S + OFF_X;
    float* HB = S + OFF_H;
    float* Q  = S + OFF_Q;
    float* K  = S + OFF_K;
    float* V  = S + OFF_V;
    float* AB = S + OFF_A;
    float* FB = S + OFF_FF;
    float* PT = S + OFF_PT;
    float* PS = S + OFF_PS;
    float* PD = S + OFF_PD;
    float* C1 = S + OFF_C1;
    float* C2 = S + OFF_C2;

    static bool attr_set = false;
    if (!attr_set) {
        cudaFuncSetAttribute(attn_tc_kernel,
                             cudaFuncAttributeMaxDynamicSharedMemorySize, ATT_SMEM_BYTES);
        attr_set = true;
    }

    embed_kernel<<<NBS, ND>>>(te, pe, ids, X);

    for (int l = 0; l < NL; l++) {
        const size_t wOff = (size_t)l * ND * ND;
        const size_t dOff = (size_t)l * ND;
        ln_kernel<<<NBS, 128>>>(X, HB, g1 + dOff, b1 + dOff);
        run_big_gemm(HB, wq + wOff, bq + dOff, nullptr, Q, NBS, ND, ND, 0);
        run_big_gemm(HB, wk + wOff, bk + dOff, nullptr, K, NBS, ND, ND, 0);
        run_big_gemm(HB, wv + wOff, bv + dOff, nullptr, V, NBS, ND, ND, 0);
        attn_tc_kernel<<<dim3(NS / 128, NH, NB), 256, ATT_SMEM_BYTES>>>(
            Q, K, V, rel + (size_t)l * (2 * NML - 1) * NDK, ids, AB);
        run_big_gemm(AB, wo + wOff, bo + dOff, X, X, NBS, ND, ND, 2);
        ln_kernel<<<NBS, 128>>>(X, HB, g2 + dOff, b2 + dOff);
        run_big_gemm(HB, fw1 + (size_t)l * ND * NFF, fb1 + (size_t)l * NFF, nullptr, FB,
                     NBS, NFF, ND, 1);
        run_big_gemm(FB, fw2 + (size_t)l * NFF * ND, fb2 + dOff, X, X, NBS, ND, NFF, 2);
    }

    ln_kernel<<<NBS, 128>>>(X, HB, fg, fbn);

    for (int i = 0; i < 4; i++)
        run_small_gemm(HB, pw1 + (size_t)i * ND * 96, pb1 + (size_t)i * 96,
                       PT + (size_t)i * NBS * 96, NBS, 96, ND, 3);
    pool_score_kernel<<<(4 * NBS + 3) / 4, 128>>>(PT, pw2, pb2, PS);
    pool_kernel<<<dim3(4, NB), 256>>>(HB, PS, ids, PD);

    run_small_gemm(PD, cw1, cb1, C1, NB, ND, 4 * ND, 1);
    run_small_gemm(C1, cw2, cb2, C2, NB, 192, ND, 1);
    run_small_gemm(C2, cw3, cb3, (float*)d_out, NB, NNC, 192, 0);
}

// round 8
// speedup vs baseline: 3.3477x; 1.0585x over previous
#include <cuda_runtime.h>
#include <math.h>
#include <stdint.h>

// ---------------- problem dims ----------------
#define NB   16
#define NS   768
#define ND   384
#define NH   12
#define NDK  32
#define NFF  1024
#define NL   6
#define NML  768
#define NNC  10
#define NBS  (NB*NS)          // 12288 rows

// ---------------- scratch ----------------
#define OFF_X   ((size_t)0)
#define OFF_H   (OFF_X  + (size_t)NBS*ND)
#define OFF_Q   (OFF_H  + (size_t)NBS*ND)
#define OFF_K   (OFF_Q  + (size_t)NBS*ND)
#define OFF_V   (OFF_K  + (size_t)NBS*ND)
#define OFF_A   (OFF_V  + (size_t)NBS*ND)
#define OFF_FF  (OFF_A  + (size_t)NBS*ND)
#define OFF_PT  (OFF_FF + (size_t)NBS*NFF)
#define OFF_PS  (OFF_PT + (size_t)4*NBS*96)
#define OFF_PD  (OFF_PS + (size_t)4*NBS)
#define OFF_C1  (OFF_PD + (size_t)NB*4*ND)
#define OFF_C2  (OFF_C1 + (size_t)NB*ND)
#define SCRATCH_TOTAL (OFF_C2 + (size_t)NB*192)

static __device__ float g_scratch[SCRATCH_TOTAL];

// ---------------- tf32 helpers ----------------
__device__ __forceinline__ float f2tf(float f) {
    uint32_t u;
    asm("cvt.rna.tf32.f32 %0, %1;" : "=r"(u) : "f"(f));
    return __uint_as_float(u);
}

__device__ __forceinline__ void mma_tf32(float* c, const float* a, const float* b) {
    asm volatile(
        "mma.sync.aligned.m16n8k8.row.col.f32.tf32.tf32.f32 "
        "{%0,%1,%2,%3}, {%4,%5,%6,%7}, {%8,%9}, {%0,%1,%2,%3};"
        : "+f"(c[0]), "+f"(c[1]), "+f"(c[2]), "+f"(c[3])
        : "r"(__float_as_uint(a[0])), "r"(__float_as_uint(a[1])),
          "r"(__float_as_uint(a[2])), "r"(__float_as_uint(a[3])),
          "r"(__float_as_uint(b[0])), "r"(__float_as_uint(b[1])));
}

// ---------------- embed ----------------
__global__ void embed_kernel(const float* __restrict__ te, const float* __restrict__ pe,
                             const int* __restrict__ ids, float* __restrict__ x) {
    int row = blockIdx.x;
    int d   = threadIdx.x;
    int s   = row % NS;
    int id  = ids[row];
    x[(size_t)row * ND + d] = te[(size_t)id * ND + d] + pe[(size_t)s * ND + d];
}

// ---------------- layernorm (float4, 128 thr/row) ----------------
__device__ __forceinline__ float block_sum128(float v, float* red) {
    #pragma unroll
    for (int o = 16; o > 0; o >>= 1) v += __shfl_xor_sync(0xffffffffu, v, o);
    int w = threadIdx.x >> 5;
    if ((threadIdx.x & 31) == 0) red[w] = v;
    __syncthreads();
    float t = red[0] + red[1] + red[2] + red[3];
    __syncthreads();
    return t;
}

__global__ void ln_kernel(const float* __restrict__ in, float* __restrict__ out,
                          const float* __restrict__ g, const float* __restrict__ b) {
    __shared__ float red[4];
    int row = blockIdx.x;
    const float4* p = (const float4*)(in + (size_t)row * ND);
    int i = threadIdx.x;
    float4 v4 = (i < 96) ? p[i] : make_float4(0.f, 0.f, 0.f, 0.f);
    float s = v4.x + v4.y + v4.z + v4.w;
    float mean = block_sum128(s, red) * (1.f / ND);
    float vs = 0.f;
    if (i < 96) {
        float a = v4.x - mean, bb = v4.y - mean, c = v4.z - mean, d = v4.w - mean;
        vs = a * a + bb * bb + c * c + d * d;
    }
    float var = block_sum128(vs, red) * (1.f / ND);
    float inv = rsqrtf(var + 1e-5f);
    if (i < 96) {
        float4 gv = ((const float4*)g)[i];
        float4 bv = ((const float4*)b)[i];
        float4 o;
        o.x = (v4.x - mean) * inv * gv.x + bv.x;
        o.y = (v4.y - mean) * inv * gv.y + bv.y;
        o.z = (v4.z - mean) * inv * gv.z + bv.z;
        o.w = (v4.w - mean) * inv * gv.w + bv.w;
        ((float4*)(out + (size_t)row * ND))[i] = o;
    }
}

// ================= tf32 tensor-core GEMM: 256x128 tile, BK=16 =================
// 8 warps in 4x2, warp tile 64x64. Requires M%256==0, N%128==0, K%16==0.
// A smem fragment-major: slot(k<16,m<256) =
//   (k>>3)*2048 + (m>>4)*128 + (m&7)*16 + (((k&3)^(((m&7)>>1)&3))<<2)
//   + ((k>>2)&1)*2 + ((m>>3)&1)
#define GSTRIDE 136
#define GEMM_SMEM_WORDS (2*4096 + 2*16*GSTRIDE)
#define GEMM_SMEM_BYTES (GEMM_SMEM_WORDS * 4)

template<int EPI>
__global__ void __launch_bounds__(256, 1)
gemm_tc_kernel(const float* __restrict__ A, const float* __restrict__ W,
               const float* __restrict__ bias, const float* __restrict__ res,
               float* __restrict__ C, int M, int N, int K) {
    extern __shared__ __align__(16) float dsm[];
    float* As2 = dsm;                       // [2][4096]
    float* Bsf = dsm + 8192;                // [2][16][GSTRIDE]

    const int t    = threadIdx.x;
    const int lane = t & 31;
    const int warp = t >> 5;
    const int wn   = (warp & 1) * 64;
    const int gid  = lane >> 2;
    const int tig  = lane & 3;
    const int brow = blockIdx.y * 256;
    const int bcol = blockIdx.x * 128;

    // A loader: thread t owns global row brow+t, all 16 k
    const int ar  = t;
    const int asw = ((ar & 7) >> 1) & 3;
    const int amb = (ar >> 4) * 128 + (ar & 7) * 16 + ((ar >> 3) & 1);
    // B loader
    const int bkr = t >> 5;
    const int bc  = lane * 4;

    // fragment read base: mblk = (warp>>1)*4 + mt
    const int afrag = (warp >> 1) * 512 + gid * 16 + ((tig ^ ((gid >> 1) & 3)) << 2);

    const float* Ap = A + (size_t)(brow + ar) * K;

    float acc[4][8][4];
    #pragma unroll
    for (int i = 0; i < 4; i++)
        #pragma unroll
        for (int j = 0; j < 8; j++)
            #pragma unroll
            for (int r = 0; r < 4; r++) acc[i][j][r] = 0.f;

    const int ntiles = K / 16;

    // ---- prologue: tile 0 -> buf 0 ----
    {
        #pragma unroll
        for (int q = 0; q < 4; q++) {
            float4 aq = *(const float4*)&Ap[q * 4];
            const float* ae = &aq.x;
            int base = (q >> 1) * 2048 + amb + (q & 1) * 2;
            #pragma unroll
            for (int j = 0; j < 4; j++)
                As2[base + ((j ^ asw) << 2)] = f2tf(ae[j]);
        }
        float4 b0 = *(const float4*)&W[(size_t)bkr * N + bcol + bc];
        float4 b1 = *(const float4*)&W[(size_t)(bkr + 8) * N + bcol + bc];
        float4 c0, c1;
        c0.x = f2tf(b0.x); c0.y = f2tf(b0.y); c0.z = f2tf(b0.z); c0.w = f2tf(b0.w);
        c1.x = f2tf(b1.x); c1.y = f2tf(b1.y); c1.z = f2tf(b1.z); c1.w = f2tf(b1.w);
        *(float4*)&Bsf[bkr * GSTRIDE + bc]       = c0;
        *(float4*)&Bsf[(bkr + 8) * GSTRIDE + bc] = c1;
    }
    __syncthreads();

    for (int tt = 0; tt < ntiles; tt++) {
        const int cur = tt & 1;
        const int nxt = cur ^ 1;
        const bool more = (tt + 1 < ntiles);
        float4 apre[4], b0, b1;
        if (more) {
            const int k0 = (tt + 1) * 16;
            #pragma unroll
            for (int q = 0; q < 4; q++) apre[q] = *(const float4*)&Ap[k0 + q * 4];
            b0 = *(const float4*)&W[(size_t)(k0 + bkr) * N + bcol + bc];
            b1 = *(const float4*)&W[(size_t)(k0 + bkr + 8) * N + bcol + bc];
        }
        const float* Ab = As2 + cur * 4096;
        const float* Bb = Bsf + cur * (16 * GSTRIDE);
        #pragma unroll
        for (int ks = 0; ks < 2; ks++) {
            float a[4][4], b[8][2];
            #pragma unroll
            for (int mt = 0; mt < 4; mt++) {
                float4 av = *(const float4*)&Ab[ks * 2048 + mt * 128 + afrag];
                a[mt][0] = av.x; a[mt][1] = av.y; a[mt][2] = av.z; a[mt][3] = av.w;
            }
            #pragma unroll
            for (int nt = 0; nt < 8; nt++) {
                const int n0 = wn + nt * 8 + gid;
                b[nt][0] = Bb[(ks * 8 + tig) * GSTRIDE + n0];
                b[nt][1] = Bb[(ks * 8 + tig + 4) * GSTRIDE + n0];
            }
            #pragma unroll
            for (int mt = 0; mt < 4; mt++)
                #pragma unroll
                for (int nt = 0; nt < 8; nt++)
                    mma_tf32(acc[mt][nt], a[mt], b[nt]);
        }
        if (more) {
            float* An = As2 + nxt * 4096;
            #pragma unroll
            for (int q = 0; q < 4; q++) {
                const float* ae = &apre[q].x;
                int base = (q >> 1) * 2048 + amb + (q & 1) * 2;
                #pragma unroll
                for (int j = 0; j < 4; j++)
                    An[base + ((j ^ asw) << 2)] = f2tf(ae[j]);
            }
            float4 c0, c1;
            c0.x = f2tf(b0.x); c0.y = f2tf(b0.y); c0.z = f2tf(b0.z); c0.w = f2tf(b0.w);
            c1.x = f2tf(b1.x); c1.y = f2tf(b1.y); c1.z = f2tf(b1.z); c1.w = f2tf(b1.w);
            float* Bn = Bsf + nxt * (16 * GSTRIDE);
            *(float4*)&Bn[bkr * GSTRIDE + bc]       = c0;
            *(float4*)&Bn[(bkr + 8) * GSTRIDE + bc] = c1;
        }
        __syncthreads();
    }

    // ---- epilogue ----
    const int wm = (warp >> 1) * 64;
    #pragma unroll
    for (int mt = 0; mt < 4; mt++) {
        const int r0 = brow + wm + mt * 16 + gid;
        #pragma unroll
        for (int nt = 0; nt < 8; nt++) {
            const int c0 = bcol + wn + nt * 8 + tig * 2;
            float bx = bias[c0], by = bias[c0 + 1];
            float v00 = acc[mt][nt][0] + bx;
            float v01 = acc[mt][nt][1] + by;
            float v10 = acc[mt][nt][2] + bx;
            float v11 = acc[mt][nt][3] + by;
            if (EPI == 1) {
                v00 = 0.5f * v00 * (1.f + erff(v00 * 0.70710678118654752f));
                v01 = 0.5f * v01 * (1.f + erff(v01 * 0.70710678118654752f));
                v10 = 0.5f * v10 * (1.f + erff(v10 * 0.70710678118654752f));
                v11 = 0.5f * v11 * (1.f + erff(v11 * 0.70710678118654752f));
            } else if (EPI == 2) {
                float2 r0v = *(const float2*)&res[(size_t)r0 * N + c0];
                float2 r1v = *(const float2*)&res[(size_t)(r0 + 8) * N + c0];
                v00 += r0v.x; v01 += r0v.y; v10 += r1v.x; v11 += r1v.y;
            }
            *(float2*)&C[(size_t)r0 * N + c0]       = make_float2(v00, v01);
            *(float2*)&C[(size_t)(r0 + 8) * N + c0] = make_float2(v10, v11);
        }
    }
}

// ---------------- small guarded SGEMM (pool/classifier) ----------------
template<int EPI>
__global__ void gemm_kernel(const float* __restrict__ A, const float* __restrict__ W,
                            const float* __restrict__ bias,
                            float* __restrict__ C, int M, int N, int K) {
    __shared__ float As[16][65];
    __shared__ float Bs[16][64];
    const int brow = blockIdx.y * 64;
    const int bcol = blockIdx.x * 64;
    const int t  = threadIdx.x;
    const int ty = t >> 4, tx = t & 15;
    float acc[4][4] = {};
    for (int k0 = 0; k0 < K; k0 += 16) {
        #pragma unroll
        for (int l = t; l < 1024; l += 256) {
            int r = l >> 4, kk = l & 15;
            int gr = brow + r;
            As[kk][r] = (gr < M && k0 + kk < K) ? A[(size_t)gr * K + k0 + kk] : 0.f;
        }
        #pragma unroll
        for (int l = t; l < 1024; l += 256) {
            int kk = l >> 6, c = l & 63;
            int gc = bcol + c;
            Bs[kk][c] = (gc < N && k0 + kk < K) ? W[(size_t)(k0 + kk) * N + gc] : 0.f;
        }
        __syncthreads();
        #pragma unroll
        for (int kk = 0; kk < 16; kk++) {
            float a[4], bvals[4];
            #pragma unroll
            for (int i = 0; i < 4; i++) a[i] = As[kk][ty * 4 + i];
            #pragma unroll
            for (int j = 0; j < 4; j++) bvals[j] = Bs[kk][tx * 4 + j];
            #pragma unroll
            for (int i = 0; i < 4; i++)
                #pragma unroll
                for (int j = 0; j < 4; j++)
                    acc[i][j] += a[i] * bvals[j];
        }
        __syncthreads();
    }
    #pragma unroll
    for (int i = 0; i < 4; i++) {
        int row = brow + ty * 4 + i;
        if (row >= M) continue;
        #pragma unroll
        for (int j = 0; j < 4; j++) {
            int col = bcol + tx * 4 + j;
            if (col >= N) continue;
            float v = acc[i][j] + bias[col];
            if (EPI == 1) v = 0.5f * v * (1.f + erff(v * 0.70710678118654752f));
            else if (EPI == 3) v = tanhf(v);
            C[(size_t)row * N + col] = v;
        }
    }
}

// ================= tensor-core flash attention with banded rel bias =================
#define ATT_SMEM_WORDS 25920
#define ATT_SMEM_BYTES (ATT_SMEM_WORDS * 4)

__global__ void __launch_bounds__(256)
attn_tc_kernel(const float* __restrict__ q, const float* __restrict__ k,
               const float* __restrict__ v, const float* __restrict__ rel,
               const int* __restrict__ ids, float* __restrict__ out) {
    extern __shared__ float sm[];
    float* Qs = sm;                   // [32][132] (d-major, transposed)
    float* Ks = sm + 4224;            // [32][68]
    float* Rs = sm + 6400;            // [32][200]
    float* Vs = sm + 12800;           // [64][36]
    float* WS = sm + 15104;           // [8][16][84]
    int*   Mk = (int*)(sm + 25856);   // [64]

    const int q0 = blockIdx.x * 128;
    const int h  = blockIdx.y;
    const int b  = blockIdx.z;
    const int t    = threadIdx.x;
    const int lane = t & 31;
    const int w    = t >> 5;
    const int gid  = lane >> 2;
    const int tig  = lane & 3;
    float* WSw = WS + w * (16 * 84);
    const int j0w = 112 - 16 * w;     // warp band offset into block rel band
    const float scale = 0.17677669529663689f;

    // ---- load Q tile (transposed, tf32) ----
    {
        const float* qb = q + ((size_t)(b * NS + q0)) * ND + h * NDK;
        #pragma unroll
        for (int i = t; i < 1024; i += 256) {
            int r = i >> 3, d0 = (i & 7) * 4;
            float4 x = *(const float4*)&qb[(size_t)r * ND + d0];
            Qs[(d0 + 0) * 132 + r] = f2tf(x.x);
            Qs[(d0 + 1) * 132 + r] = f2tf(x.y);
            Qs[(d0 + 2) * 132 + r] = f2tf(x.z);
            Qs[(d0 + 3) * 132 + r] = f2tf(x.w);
        }
    }
    __syncthreads();

    // ---- Q fragments: loaded ONCE ----
    float af[4][4];
    #pragma unroll
    for (int ks = 0; ks < 4; ks++) {
        int kk = ks * 8 + tig;
        int m0 = w * 16 + gid;
        af[ks][0] = Qs[kk * 132 + m0];
        af[ks][1] = Qs[kk * 132 + m0 + 8];
        af[ks][2] = Qs[(kk + 4) * 132 + m0];
        af[ks][3] = Qs[(kk + 4) * 132 + m0 + 8];
    }

    float m_lo = -INFINITY, m_hi = -INFINITY, l_lo = 0.f, l_hi = 0.f;
    float oa[4][4];
    #pragma unroll
    for (int i = 0; i < 4; i++)
        #pragma unroll
        for (int j = 0; j < 4; j++) oa[i][j] = 0.f;

    for (int k0 = 0; k0 < NS; k0 += 64) {
        __syncthreads();
        // ---- load K (transposed) and V (row-major) tiles ----
        {
            const float* kb = k + ((size_t)(b * NS + k0)) * ND + h * NDK;
            const float* vb = v + ((size_t)(b * NS + k0)) * ND + h * NDK;
            #pragma unroll
            for (int i = t; i < 512; i += 256) {
                int r = i >> 3, d0 = (i & 7) * 4;
                float4 x = *(const float4*)&kb[(size_t)r * ND + d0];
                Ks[(d0 + 0) * 68 + r] = f2tf(x.x);
                Ks[(d0 + 1) * 68 + r] = f2tf(x.y);
                Ks[(d0 + 2) * 68 + r] = f2tf(x.z);
                Ks[(d0 + 3) * 68 + r] = f2tf(x.w);
                float4 y = *(const float4*)&vb[(size_t)r * ND + d0];
                float4 z;
                z.x = f2tf(y.x); z.y = f2tf(y.y); z.z = f2tf(y.z); z.w = f2tf(y.w);
                *(float4*)&Vs[r * 36 + d0] = z;
            }
            // rel band rows: delta = k0 - q0 + 640 + j, j in [0,191)
            const float* rb = rel + (size_t)(k0 - q0 + 640) * NDK;
            for (int i = t; i < 191 * 8; i += 256) {
                int j = i >> 3, d0 = (i & 7) * 4;
                float4 x = *(const float4*)&rb[(size_t)j * NDK + d0];
                Rs[(d0 + 0) * 200 + j] = f2tf(x.x);
                Rs[(d0 + 1) * 200 + j] = f2tf(x.y);
                Rs[(d0 + 2) * 200 + j] = f2tf(x.z);
                Rs[(d0 + 3) * 200 + j] = f2tf(x.w);
            }
            if (t < 64) Mk[t] = ids[b * NS + k0 + t];
        }
        __syncthreads();

        // ---- rel-band MMA: P[16 x 80] ----
        {
            float rc[10][4];
            #pragma unroll
            for (int nt = 0; nt < 10; nt++)
                #pragma unroll
                for (int e = 0; e < 4; e++) rc[nt][e] = 0.f;
            #pragma unroll
            for (int ks = 0; ks < 4; ks++) {
                int kk = ks * 8 + tig;
                #pragma unroll
                for (int nt = 0; nt < 10; nt++) {
                    int col = j0w + nt * 8 + gid;
                    float bb[2];
                    bb[0] = Rs[kk * 200 + col];
                    bb[1] = Rs[(kk + 4) * 200 + col];
                    mma_tf32(rc[nt], af[ks], bb);
                }
            }
            #pragma unroll
            for (int nt = 0; nt < 10; nt++) {
                int c0 = nt * 8 + 2 * tig;
                WSw[gid * 84 + c0]           = rc[nt][0];
                WSw[gid * 84 + c0 + 1]       = rc[nt][1];
                WSw[(gid + 8) * 84 + c0]     = rc[nt][2];
                WSw[(gid + 8) * 84 + c0 + 1] = rc[nt][3];
            }
        }
        __syncwarp();

        // ---- QK MMA: S1[16 x 64] ----
        float qa[8][4];
        #pragma unroll
        for (int nt = 0; nt < 8; nt++)
            #pragma unroll
            for (int e = 0; e < 4; e++) qa[nt][e] = 0.f;
        #pragma unroll
        for (int ks = 0; ks < 4; ks++) {
            int kk = ks * 8 + tig;
            #pragma unroll
            for (int nt = 0; nt < 8; nt++) {
                int col = nt * 8 + gid;
                float bb[2];
                bb[0] = Ks[kk * 68 + col];
                bb[1] = Ks[(kk + 4) * 68 + col];
                mma_tf32(qa[nt], af[ks], bb);
            }
        }

        // ---- combine: S = scale*(S1 + band[r][k+15-r]), mask ----
        #pragma unroll
        for (int nt = 0; nt < 8; nt++) {
            int kl0 = nt * 8 + 2 * tig;
            int kl1 = kl0 + 1;
            int rlo = gid, rhi = gid + 8;
            bool m0b = (Mk[kl0] == 0), m1b = (Mk[kl1] == 0);
            qa[nt][0] = m0b ? -INFINITY : (qa[nt][0] + WSw[rlo * 84 + kl0 + 15 - rlo]) * scale;
            qa[nt][1] = m1b ? -INFINITY : (qa[nt][1] + WSw[rlo * 84 + kl1 + 15 - rlo]) * scale;
            qa[nt][2] = m0b ? -INFINITY : (qa[nt][2] + WSw[rhi * 84 + kl0 + 15 - rhi]) * scale;
            qa[nt][3] = m1b ? -INFINITY : (qa[nt][3] + WSw[rhi * 84 + kl1 + 15 - rhi]) * scale;
        }
        __syncwarp();

        // ---- online softmax ----
        float tm_lo = -INFINITY, tm_hi = -INFINITY;
        #pragma unroll
        for (int nt = 0; nt < 8; nt++) {
            tm_lo = fmaxf(tm_lo, fmaxf(qa[nt][0], qa[nt][1]));
            tm_hi = fmaxf(tm_hi, fmaxf(qa[nt][2], qa[nt][3]));
        }
        tm_lo = fmaxf(tm_lo, __shfl_xor_sync(0xffffffffu, tm_lo, 1));
        tm_lo = fmaxf(tm_lo, __shfl_xor_sync(0xffffffffu, tm_lo, 2));
        tm_hi = fmaxf(tm_hi, __shfl_xor_sync(0xffffffffu, tm_hi, 1));
        tm_hi = fmaxf(tm_hi, __shfl_xor_sync(0xffffffffu, tm_hi, 2));

        float nm_lo = fmaxf(m_lo, tm_lo);
        float nm_hi = fmaxf(m_hi, tm_hi);
        float c_lo = 1.f, c_hi = 1.f, sum_lo = 0.f, sum_hi = 0.f;

        if (nm_lo == -INFINITY) {
            #pragma unroll
            for (int nt = 0; nt < 8; nt++) {
                int c0 = nt * 8 + 2 * tig;
                WSw[gid * 84 + c0] = 0.f; WSw[gid * 84 + c0 + 1] = 0.f;
            }
        } else {
            c_lo = __expf(m_lo - nm_lo);
            #pragma unroll
            for (int nt = 0; nt < 8; nt++) {
                int c0 = nt * 8 + 2 * tig;
                float p0 = __expf(qa[nt][0] - nm_lo);
                float p1 = __expf(qa[nt][1] - nm_lo);
                sum_lo += p0 + p1;
                WSw[gid * 84 + c0]     = f2tf(p0);
                WSw[gid * 84 + c0 + 1] = f2tf(p1);
            }
        }
        if (nm_hi == -INFINITY) {
            #pragma unroll
            for (int nt = 0; nt < 8; nt++) {
                int c0 = nt * 8 + 2 * tig;
                WSw[(gid + 8) * 84 + c0] = 0.f; WSw[(gid + 8) * 84 + c0 + 1] = 0.f;
            }
        } else {
            c_hi = __expf(m_hi - nm_hi);
            #pragma unroll
            for (int nt = 0; nt < 8; nt++) {
                int c0 = nt * 8 + 2 * tig;
                float p0 = __expf(qa[nt][2] - nm_hi);
                float p1 = __expf(qa[nt][3] - nm_hi);
                sum_hi += p0 + p1;
                WSw[(gid + 8) * 84 + c0]     = f2tf(p0);
                WSw[(gid + 8) * 84 + c0 + 1] = f2tf(p1);
            }
        }
        sum_lo += __shfl_xor_sync(0xffffffffu, sum_lo, 1);
        sum_lo += __shfl_xor_sync(0xffffffffu, sum_lo, 2);
        sum_hi += __shfl_xor_sync(0xffffffffu, sum_hi, 1);
        sum_hi += __shfl_xor_sync(0xffffffffu, sum_hi, 2);
        m_lo = nm_lo; m_hi = nm_hi;
        l_lo = l_lo * c_lo + sum_lo;
        l_hi = l_hi * c_hi + sum_hi;
        #pragma unroll
        for (int nt = 0; nt < 4; nt++) {
            oa[nt][0] *= c_lo; oa[nt][1] *= c_lo;
            oa[nt][2] *= c_hi; oa[nt][3] *= c_hi;
        }
        __syncwarp();

        // ---- PV MMA: O[16 x 32] += P[16 x 64] @ V[64 x 32] ----
        #pragma unroll
        for (int ks = 0; ks < 8; ks++) {
            int kk = ks * 8 + tig;
            float pa[4];
            pa[0] = WSw[gid * 84 + kk];
            pa[1] = WSw[(gid + 8) * 84 + kk];
            pa[2] = WSw[gid * 84 + kk + 4];
            pa[3] = WSw[(gid + 8) * 84 + kk + 4];
            #pragma unroll
            for (int nt = 0; nt < 4; nt++) {
                int col = nt * 8 + gid;
                float bb[2];
                bb[0] = Vs[kk * 36 + col];
                bb[1] = Vs[(kk + 4) * 36 + col];
                mma_tf32(oa[nt], pa, bb);
            }
        }
    }

    // ---- finalize ----
    float inv_lo = (l_lo > 0.f) ? 1.f / l_lo : 0.f;
    float inv_hi = (l_hi > 0.f) ? 1.f / l_hi : 0.f;
    const int rlo = b * NS + q0 + w * 16 + gid;
    #pragma unroll
    for (int nt = 0; nt < 4; nt++) {
        int col = h * NDK + nt * 8 + 2 * tig;
        out[(size_t)rlo * ND + col]           = oa[nt][0] * inv_lo;
        out[(size_t)rlo * ND + col + 1]       = oa[nt][1] * inv_lo;
        out[(size_t)(rlo + 8) * ND + col]     = oa[nt][2] * inv_hi;
        out[(size_t)(rlo + 8) * ND + col + 1] = oa[nt][3] * inv_hi;
    }
}

// ---------------- pooling ----------------
__global__ void pool_score_kernel(const float* __restrict__ tmp, const float* __restrict__ pw2,
                                  const float* __restrict__ pb2, float* __restrict__ scores) {
    int gid = blockIdx.x * (blockDim.x >> 5) + (threadIdx.x >> 5);
    if (gid >= 4 * NBS) return;
    int head = gid / NBS;
    int lane = threadIdx.x & 31;
    const float* p = tmp + (size_t)gid * 96;
    float s = 0.f;
    for (int j = lane; j < 96; j += 32) s += p[j] * pw2[head * 96 + j];
    #pragma unroll
    for (int o = 16; o > 0; o >>= 1) s += __shfl_xor_sync(0xffffffffu, s, o);
    if (lane == 0) scores[gid] = s + pb2[head];
}

__global__ void pool_kernel(const float* __restrict__ x, const float* __restrict__ scores,
                            const int* __restrict__ ids, float* __restrict__ pooled) {
    const int head = blockIdx.x;
    const int b    = blockIdx.y;
    __shared__ float ps[NS];
    __shared__ float red[8];
    const float* sc = scores + (size_t)head * NBS + (size_t)b * NS;

    float m = -INFINITY;
    for (int s = threadIdx.x; s < NS; s += 256) {
        float val = (ids[b * NS + s] == 0) ? -INFINITY : sc[s];
        ps[s] = val;
        m = fmaxf(m, val);
    }
    #pragma unroll
    for (int o = 16; o > 0; o >>= 1) m = fmaxf(m, __shfl_xor_sync(0xffffffffu, m, o));
    if ((threadIdx.x & 31) == 0) red[threadIdx.x >> 5] = m;
    __syncthreads();
    float M = -INFINITY;
    #pragma unroll
    for (int i = 0; i < 8; i++) M = fmaxf(M, red[i]);
    __syncthreads();

    float sum = 0.f;
    for (int s = threadIdx.x; s < NS; s += 256) {
        float p = __expf(ps[s] - M);
        ps[s] = p;
        sum += p;
    }
    #pragma unroll
    for (int o = 16; o > 0; o >>= 1) sum += __shfl_xor_sync(0xffffffffu, sum, o);
    if ((threadIdx.x & 31) == 0) red[threadIdx.x >> 5] = sum;
    __syncthreads();
    float T = 0.f;
    #pragma unroll
    for (int i = 0; i < 8; i++) T += red[i];
    __syncthreads();
    float inv = 1.f / T;

    for (int d = threadIdx.x; d < ND; d += 256) {
        float acc = 0.f;
        const float* xp = x + (size_t)b * NS * ND + d;
        for (int s = 0; s < NS; s++) acc += ps[s] * xp[(size_t)s * ND];
        pooled[(size_t)b * (4 * ND) + head * ND + d] = acc * inv;
    }
}

// ---------------- dispatchers ----------------
static void run_big_gemm(const float* A, const float* W, const float* bias, const float* res,
                         float* C, int M, int N, int K, int epi) {
    dim3 grid(N / 128, M / 256);
    switch (epi) {
        case 0: gemm_tc_kernel<0><<<grid, 256, GEMM_SMEM_BYTES>>>(A, W, bias, res, C, M, N, K); break;
        case 1: gemm_tc_kernel<1><<<grid, 256, GEMM_SMEM_BYTES>>>(A, W, bias, res, C, M, N, K); break;
        case 2: gemm_tc_kernel<2><<<grid, 256, GEMM_SMEM_BYTES>>>(A, W, bias, res, C, M, N, K); break;
    }
}

static void run_small_gemm(const float* A, const float* W, const float* bias,
                           float* C, int M, int N, int K, int epi) {
    dim3 grid((N + 63) / 64, (M + 63) / 64);
    switch (epi) {
        case 0: gemm_kernel<0><<<grid, 256>>>(A, W, bias, C, M, N, K); break;
        case 1: gemm_kernel<1><<<grid, 256>>>(A, W, bias, C, M, N, K); break;
        case 3: gemm_kernel<3><<<grid, 256>>>(A, W, bias, C, M, N, K); break;
    }
}

// ---------------- entry ----------------
extern "C" void kernel_launch(void* const* d_in, const int* in_sizes, int n_in,
                              void* d_out, int out_size) {
    const float* te   = (const float*)d_in[0];
    const float* pe   = (const float*)d_in[1];
    const float* wq   = (const float*)d_in[2];
    const float* bq   = (const float*)d_in[3];
    const float* wk   = (const float*)d_in[4];
    const float* bk   = (const float*)d_in[5];
    const float* wv   = (const float*)d_in[6];
    const float* bv   = (const float*)d_in[7];
    const float* wo   = (const float*)d_in[8];
    const float* bo   = (const float*)d_in[9];
    const float* rel  = (const float*)d_in[10];
    const float* g1   = (const float*)d_in[11];
    const float* b1   = (const float*)d_in[12];
    const float* g2   = (const float*)d_in[13];
    const float* b2   = (const float*)d_in[14];
    const float* fw1  = (const float*)d_in[15];
    const float* fb1  = (const float*)d_in[16];
    const float* fw2  = (const float*)d_in[17];
    const float* fb2  = (const float*)d_in[18];
    const float* fg   = (const float*)d_in[19];
    const float* fbn  = (const float*)d_in[20];
    const float* pw1  = (const float*)d_in[21];
    const float* pb1  = (const float*)d_in[22];
    const float* pw2  = (const float*)d_in[23];
    const float* pb2  = (const float*)d_in[24];
    const float* cw1  = (const float*)d_in[25];
    const float* cb1  = (const float*)d_in[26];
    const float* cw2  = (const float*)d_in[27];
    const float* cb2  = (const float*)d_in[28];
    const float* cw3  = (const float*)d_in[29];
    const float* cb3  = (const float*)d_in[30];
    const int*   ids  = (const int*)d_in[31];

    float* S;
    cudaGetSymbolAddress((void**)&S, g_scratch);
    float* X  = S + OFF_X;
    float* HB = S + OFF_H;
    float* Q  = S + OFF_Q;
    float* K  = S + OFF_K;
    float* V  = S + OFF_V;
    float* AB = S + OFF_A;
    float* FB = S + OFF_FF;
    float* PT = S + OFF_PT;
    float* PS = S + OFF_PS;
    float* PD = S + OFF_PD;
    float* C1 = S + OFF_C1;
    float* C2 = S + OFF_C2;

    cudaFuncSetAttribute(attn_tc_kernel,
                         cudaFuncAttributeMaxDynamicSharedMemorySize, ATT_SMEM_BYTES);
    cudaFuncSetAttribute(gemm_tc_kernel<0>,
                         cudaFuncAttributeMaxDynamicSharedMemorySize, GEMM_SMEM_BYTES);
    cudaFuncSetAttribute(gemm_tc_kernel<1>,
                         cudaFuncAttributeMaxDynamicSharedMemorySize, GEMM_SMEM_BYTES);
    cudaFuncSetAttribute(gemm_tc_kernel<2>,
                         cudaFuncAttributeMaxDynamicSharedMemorySize, GEMM_SMEM_BYTES);

    embed_kernel<<<NBS, ND>>>(te, pe, ids, X);

    for (int l = 0; l < NL; l++) {
        const size_t wOff = (size_t)l * ND * ND;
        const size_t dOff = (size_t)l * ND;
        ln_kernel<<<NBS, 128>>>(X, HB, g1 + dOff, b1 + dOff);
        run_big_gemm(HB, wq + wOff, bq + dOff, nullptr, Q, NBS, ND, ND, 0);
        run_big_gemm(HB, wk + wOff, bk + dOff, nullptr, K, NBS, ND, ND, 0);
        run_big_gemm(HB, wv + wOff, bv + dOff, nullptr, V, NBS, ND, ND, 0);
        attn_tc_kernel<<<dim3(NS / 128, NH, NB), 256, ATT_SMEM_BYTES>>>(
            Q, K, V, rel + (size_t)l * (2 * NML - 1) * NDK, ids, AB);
        run_big_gemm(AB, wo + wOff, bo + dOff, X, X, NBS, ND, ND, 2);
        ln_kernel<<<NBS, 128>>>(X, HB, g2 + dOff, b2 + dOff);
        run_big_gemm(HB, fw1 + (size_t)l * ND * NFF, fb1 + (size_t)l * NFF, nullptr, FB,
                     NBS, NFF, ND, 1);
        run_big_gemm(FB, fw2 + (size_t)l * NFF * ND, fb2 + dOff, X, X, NBS, ND, NFF, 2);
    }

    ln_kernel<<<NBS, 128>>>(X, HB, fg, fbn);

    for (int i = 0; i < 4; i++)
        run_small_gemm(HB, pw1 + (size_t)i * ND * 96, pb1 + (size_t)i * 96,
                       PT + (size_t)i * NBS * 96, NBS, 96, ND, 3);
    pool_score_kernel<<<(4 * NBS + 3) / 4, 128>>>(PT, pw2, pb2, PS);
    pool_kernel<<<dim3(4, NB), 256>>>(HB, PS, ids, PD);

    run_small_gemm(PD, cw1, cb1, C1, NB, ND, 4 * ND, 1);
    run_small_gemm(C1, cw2, cb2, C2, NB, 192, ND, 1);
    run_small_gemm(C2, cw3, cb3, (float*)d_out, NB, NNC, 192, 0);
}